// round 13
// baseline (speedup 1.0000x reference)
#include <cuda_runtime.h>
#include <cuda_bf16.h>
#include <cuda_fp16.h>
#include <math.h>
#include <cstdint>

#define NN   50000
#define EE0  800000
#define ETOT 850000
#define NH   4
#define CAP  96      // ELL row capacity; max degree ~45 for this fixed graph

// ---------------- scratch (device globals; no allocation allowed) -------------
__device__ __align__(16) __half g_feat[(size_t)NN * 128];  // inter-layer feats (fp16)
__device__ __align__(16) __half g_h01[(size_t)NN * 128];   // layers 0/1 h (fp16)
__device__ __align__(16) __half g_h2[(size_t)NN * 40];     // layer 2 h (fp16)
__device__ __align__(16) float g_als[NN * NH];
__device__ __align__(16) float g_ald[NN * NH];
__device__ __align__(16) __nv_bfloat16 g_Whi[2][16384];
__device__ __align__(16) __nv_bfloat16 g_Wlo[2][16384];
__device__ int g_deg[NN];
__device__ int g_ell[(size_t)NN * CAP];
__device__ int g_is64;

// ---------------- small helpers -----------------------------------------------
#define MMA_BF16(d, a, b) \
    asm volatile("mma.sync.aligned.m16n8k16.row.col.f32.bf16.bf16.f32 " \
        "{%0,%1,%2,%3}, {%4,%5,%6,%7}, {%8,%9}, {%0,%1,%2,%3};" \
        : "+f"((d)[0]), "+f"((d)[1]), "+f"((d)[2]), "+f"((d)[3]) \
        : "r"((a)[0]), "r"((a)[1]), "r"((a)[2]), "r"((a)[3]), "r"((b)[0]), "r"((b)[1]))

__device__ __forceinline__ void split_bf16(float x, __nv_bfloat16& h, __nv_bfloat16& l) {
    h = __float2bfloat16(x);
    l = __float2bfloat16(x - __bfloat162float(h));
}
__device__ __forceinline__ uint32_t bfpair(__nv_bfloat16 a, __nv_bfloat16 b) {
    return (uint32_t)__bfloat16_as_ushort(a) | ((uint32_t)__bfloat16_as_ushort(b) << 16);
}

// ---------------- edge access --------------------------------------------------
__device__ __forceinline__ void get_edge(const void* ei, int e, int& s, int& d) {
    if (e >= EE0) { s = e - EE0; d = s; return; }
    if (g_is64) {
        const long long* p = (const long long*)ei;
        s = (int)p[e];
        d = (int)p[EE0 + e];
    } else {
        const int* p = (const int*)ei;
        s = p[e];
        d = p[EE0 + e];
    }
}

// ---------------- init: dtype detect + deg zero --------------------------------
__global__ void k_init(const int* __restrict__ ei32) {
    int i = blockIdx.x * blockDim.x + threadIdx.x;
    if (blockIdx.x == 0) {
        __shared__ int zc;
        if (threadIdx.x == 0) zc = 0;
        __syncthreads();
        int z = 0;
        for (int k = threadIdx.x; k < 1024; k += blockDim.x)
            if (ei32[2 * k + 1] == 0) z++;
        atomicAdd(&zc, z);
        __syncthreads();
        if (threadIdx.x == 0) g_is64 = (zc > 512) ? 1 : 0;
    }
    if (i < NN) g_deg[i] = 0;
}

// ---------------- W split (needed only by GEMMs) -------------------------------
__global__ void k_wsplit(const float* __restrict__ W0, const float* __restrict__ W1) {
    int i = blockIdx.x * blockDim.x + threadIdx.x;
    if (i < 16384) {
        split_bf16(W0[i], g_Whi[0][i], g_Wlo[0][i]);
    } else if (i < 32768) {
        split_bf16(W1[i - 16384], g_Whi[1][i - 16384], g_Wlo[1][i - 16384]);
    }
}

// ---------------- ELL build (single pass, no scan) -----------------------------
__global__ void k_fill(const void* __restrict__ ei) {
    int e = blockIdx.x * blockDim.x + threadIdx.x;
    if (e >= ETOT) return;
    int s, d;
    get_edge(ei, e, s, d);
    int pos = atomicAdd(&g_deg[d], 1);
    if (pos < CAP) g_ell[(size_t)d * CAP + pos] = s;
}

// ======= bf16x3 GEMM via mma.sync (separate hi/lo smem), fused att dots =======
#define SMH_XHI 1024
#define SMH_XLO (SMH_XHI + 128 * 136 * 2)
#define SMH_WHI (SMH_XLO + 128 * 136 * 2)
#define SMH_WLO (SMH_WHI + 128 * 136 * 2)
#define SMH_TOT (SMH_WLO + 128 * 136 * 2)   // 140288

__global__ void __launch_bounds__(512, 1)
k_gemm_mma(const float* __restrict__ xin, int use_gfeat, int widx,
           const float* __restrict__ a_src, const float* __restrict__ a_dst) {
    extern __shared__ char smem[];
    float* AS = (float*)(smem);
    float* AD = (float*)(smem + 512);
    __nv_bfloat16* Xhi = (__nv_bfloat16*)(smem + SMH_XHI);
    __nv_bfloat16* Xlo = (__nv_bfloat16*)(smem + SMH_XLO);
    __nv_bfloat16* Whi = (__nv_bfloat16*)(smem + SMH_WHI);
    __nv_bfloat16* Wlo = (__nv_bfloat16*)(smem + SMH_WLO);
    int tid = threadIdx.x;
    int row0 = blockIdx.x * 128;

    if (tid < 128) {
        AS[tid] = a_src[tid];
        AD[tid] = a_dst[tid];
    }
    // stage X: (fp32 input | fp16 g_feat) -> bf16 hi/lo in separate arrays
    for (int idx = tid; idx < 128 * 32; idx += 512) {
        int r = idx >> 5, c4 = (idx & 31) * 4;
        int row = row0 + r;
        float4 v = make_float4(0.f, 0.f, 0.f, 0.f);
        if (row < NN) {
            if (use_gfeat) {
                uint2 hv = *(const uint2*)(g_feat + (size_t)row * 128 + c4);
                float2 fa = __half22float2(*reinterpret_cast<__half2*>(&hv.x));
                float2 fb = __half22float2(*reinterpret_cast<__half2*>(&hv.y));
                v = make_float4(fa.x, fa.y, fb.x, fb.y);
            } else {
                v = *(const float4*)&xin[(size_t)row * 128 + c4];
            }
        }
        __nv_bfloat16 h0, h1, h2, h3, l0, l1, l2, l3;
        split_bf16(v.x, h0, l0);
        split_bf16(v.y, h1, l1);
        split_bf16(v.z, h2, l2);
        split_bf16(v.w, h3, l3);
        uint32_t* dh = (uint32_t*)(Xhi + r * 136 + c4);
        uint32_t* dl = (uint32_t*)(Xlo + r * 136 + c4);
        dh[0] = bfpair(h0, h1);
        dh[1] = bfpair(h2, h3);
        dl[0] = bfpair(l0, l1);
        dl[1] = bfpair(l2, l3);
    }
    {
        const __nv_bfloat16* whi = g_Whi[widx];
        const __nv_bfloat16* wlo = g_Wlo[widx];
        for (int idx = tid; idx < 2048; idx += 512) {
            int n = idx >> 4, kc = (idx & 15) * 8;
            *(uint4*)(Whi + n * 136 + kc) = *(const uint4*)(whi + n * 128 + kc);
            *(uint4*)(Wlo + n * 136 + kc) = *(const uint4*)(wlo + n * 128 + kc);
        }
    }
    __syncthreads();

    int w = tid >> 5;
    int lane = tid & 31;
    int g = lane >> 2;
    int tig = lane & 3;
    int rw = (w & 7) * 16;
    int cw = (w >> 3) * 64;

    float acc[8][4];
#pragma unroll
    for (int i = 0; i < 8; i++)
#pragma unroll
        for (int j = 0; j < 4; j++) acc[i][j] = 0.f;

#pragma unroll
    for (int kt = 0; kt < 8; kt++) {
        int kk = kt * 16 + 2 * tig;
        int rA = rw + g, rB = rA + 8;
        uint32_t ahi[4], alo[4];
        ahi[0] = *(const uint32_t*)(Xhi + rA * 136 + kk);
        ahi[1] = *(const uint32_t*)(Xhi + rB * 136 + kk);
        ahi[2] = *(const uint32_t*)(Xhi + rA * 136 + kk + 8);
        ahi[3] = *(const uint32_t*)(Xhi + rB * 136 + kk + 8);
        alo[0] = *(const uint32_t*)(Xlo + rA * 136 + kk);
        alo[1] = *(const uint32_t*)(Xlo + rB * 136 + kk);
        alo[2] = *(const uint32_t*)(Xlo + rA * 136 + kk + 8);
        alo[3] = *(const uint32_t*)(Xlo + rB * 136 + kk + 8);
#pragma unroll
        for (int nt = 0; nt < 8; nt++) {
            int nc = cw + nt * 8 + g;
            uint32_t bhi[2], blo[2];
            bhi[0] = *(const uint32_t*)(Whi + nc * 136 + kk);
            bhi[1] = *(const uint32_t*)(Whi + nc * 136 + kk + 8);
            blo[0] = *(const uint32_t*)(Wlo + nc * 136 + kk);
            blo[1] = *(const uint32_t*)(Wlo + nc * 136 + kk + 8);
            MMA_BF16(acc[nt], ahi, bhi);
            MMA_BF16(acc[nt], ahi, blo);
            MMA_BF16(acc[nt], alo, bhi);
        }
    }

    int rowA = row0 + rw + g;
    int rowB = rowA + 8;
    int h0 = (w >> 3) * 2;
    float ps0[2] = {0.f, 0.f}, ps1[2] = {0.f, 0.f};
    float pd0[2] = {0.f, 0.f}, pd1[2] = {0.f, 0.f};
#pragma unroll
    for (int nt = 0; nt < 8; nt++) {
        int h = nt >> 2;
        int c = cw + nt * 8 + 2 * tig;
        float a0 = AS[c], a1 = AS[c + 1];
        float d0 = AD[c], d1 = AD[c + 1];
        ps0[h] += acc[nt][0] * a0 + acc[nt][1] * a1;
        ps1[h] += acc[nt][2] * a0 + acc[nt][3] * a1;
        pd0[h] += acc[nt][0] * d0 + acc[nt][1] * d1;
        pd1[h] += acc[nt][2] * d0 + acc[nt][3] * d1;
        if (rowA < NN)
            *(__half2*)&g_h01[(size_t)rowA * 128 + c] = __floats2half2_rn(acc[nt][0], acc[nt][1]);
        if (rowB < NN)
            *(__half2*)&g_h01[(size_t)rowB * 128 + c] = __floats2half2_rn(acc[nt][2], acc[nt][3]);
    }
#pragma unroll
    for (int h = 0; h < 2; h++) {
        ps0[h] += __shfl_xor_sync(0xffffffffu, ps0[h], 1);
        ps0[h] += __shfl_xor_sync(0xffffffffu, ps0[h], 2);
        ps1[h] += __shfl_xor_sync(0xffffffffu, ps1[h], 1);
        ps1[h] += __shfl_xor_sync(0xffffffffu, ps1[h], 2);
        pd0[h] += __shfl_xor_sync(0xffffffffu, pd0[h], 1);
        pd0[h] += __shfl_xor_sync(0xffffffffu, pd0[h], 2);
        pd1[h] += __shfl_xor_sync(0xffffffffu, pd1[h], 1);
        pd1[h] += __shfl_xor_sync(0xffffffffu, pd1[h], 2);
    }
    if (tig == 0) {
#pragma unroll
        for (int h = 0; h < 2; h++) {
            if (rowA < NN) {
                g_als[rowA * 4 + h0 + h] = ps0[h];
                g_ald[rowA * 4 + h0 + h] = pd0[h];
            }
            if (rowB < NN) {
                g_als[rowB * 4 + h0 + h] = ps1[h];
                g_ald[rowB * 4 + h0 + h] = pd1[h];
            }
        }
    }
}

// --- single-pass softmax + aggregation, ELL + fp16 gather (layers 0/1) ---------
__global__ void __launch_bounds__(256)
k_agg(const float* __restrict__ bias) {
    int warp = (blockIdx.x * blockDim.x + threadIdx.x) >> 5;
    int lane = threadIdx.x & 31;
    if (warp >= NN) return;
    int node = warp;
    int deg = g_deg[node];
    const int* row = &g_ell[(size_t)node * CAP];

    int head = lane >> 3;
    int sub = lane & 7;
    float aldh = g_ald[node * 4 + head];
    int c4 = lane * 4;
    float4 acc = make_float4(0.f, 0.f, 0.f, 0.f);
    float den = 0.f;

    for (int base = 0; base < deg; base += 32) {
        int j = base + lane;
        int sj = (j < deg) ? row[j] : 0;
        float er[4];
#pragma unroll
        for (int k = 0; k < 4; k++) {
            int s2 = __shfl_sync(0xffffffffu, sj, sub + 8 * k);
            float e = __ldg(&g_als[s2 * 4 + head]) + aldh;
            e = (e >= 0.f) ? e : 0.2f * e;
            er[k] = (base + sub + 8 * k < deg) ? __expf(e) : 0.f;
        }
#pragma unroll
        for (int k8 = 0; k8 < 4; k8++) {
            if (base + 8 * k8 >= deg) break;
            float ek = er[k8];
            int s[8];
            float w[8];
#pragma unroll
            for (int u = 0; u < 8; u++) {
                s[u] = __shfl_sync(0xffffffffu, sj, 8 * k8 + u);
                w[u] = __shfl_sync(0xffffffffu, ek, (head << 3) | u);
            }
            uint2 hv[8];
#pragma unroll
            for (int u = 0; u < 8; u++)
                hv[u] = *(const uint2*)(g_h01 + (size_t)s[u] * 128 + c4);
#pragma unroll
            for (int u = 0; u < 8; u++) {
                float2 fa = __half22float2(*reinterpret_cast<__half2*>(&hv[u].x));
                float2 fb = __half22float2(*reinterpret_cast<__half2*>(&hv[u].y));
                den += w[u];
                acc.x = fmaf(w[u], fa.x, acc.x);
                acc.y = fmaf(w[u], fa.y, acc.y);
                acc.z = fmaf(w[u], fb.x, acc.z);
                acc.w = fmaf(w[u], fb.y, acc.w);
            }
        }
    }

    float invd = 1.f / den;
    float4 bv = *(const float4*)&bias[c4];
    float r0 = fmaf(acc.x, invd, bv.x);
    float r1 = fmaf(acc.y, invd, bv.y);
    float r2 = fmaf(acc.z, invd, bv.z);
    float r3 = fmaf(acc.w, invd, bv.w);
    r0 = (r0 > 0.f) ? r0 : expm1f(r0);
    r1 = (r1 > 0.f) ? r1 : expm1f(r1);
    r2 = (r2 > 0.f) ? r2 : expm1f(r2);
    r3 = (r3 > 0.f) ? r3 : expm1f(r3);
    uint2 o;
    *reinterpret_cast<__half2*>(&o.x) = __floats2half2_rn(r0, r1);
    *reinterpret_cast<__half2*>(&o.y) = __floats2half2_rn(r2, r3);
    *(uint2*)(g_feat + (size_t)node * 128 + c4) = o;
}

// ---------------- layer 2: GEMM (Nout=40) + fused attention dots ---------------
__global__ void __launch_bounds__(256)
k_gemm40(const float* __restrict__ W2,
         const float* __restrict__ a_src2, const float* __restrict__ a_dst2) {
    __shared__ float Wt[128 * 44];
    __shared__ float Xs[32 * 128];
    int t = threadIdx.x;
    int row0 = blockIdx.x * 32;

    for (int idx = t; idx < 40 * 128; idx += 256) {
        int c = idx >> 7, k = idx & 127;
        Wt[k * 44 + c] = W2[idx];
    }
    for (int idx = t; idx < 32 * 32; idx += 256) {
        int r = idx >> 5, c4 = (idx & 31) * 4;
        int row = row0 + r;
        float4 v = make_float4(0.f, 0.f, 0.f, 0.f);
        if (row < NN) {
            uint2 hv = *(const uint2*)(g_feat + (size_t)row * 128 + c4);
            float2 fa = __half22float2(*reinterpret_cast<__half2*>(&hv.x));
            float2 fb = __half22float2(*reinterpret_cast<__half2*>(&hv.y));
            v = make_float4(fa.x, fa.y, fb.x, fb.y);
        }
        *(float4*)&Xs[r * 128 + c4] = v;
    }

    int cg = t & 7;
    int rg = t >> 3;
    float as[5], ad[5];
#pragma unroll
    for (int j = 0; j < 5; j++) {
        as[j] = __ldg(&a_src2[cg * 5 + j]);
        ad[j] = __ldg(&a_dst2[cg * 5 + j]);
    }
    __syncthreads();

    float acc[5] = {0.f, 0.f, 0.f, 0.f, 0.f};
#pragma unroll 4
    for (int k = 0; k < 128; k++) {
        float a = Xs[rg * 128 + k];
#pragma unroll
        for (int j = 0; j < 5; j++)
            acc[j] = fmaf(a, Wt[k * 44 + cg * 5 + j], acc[j]);
    }

    float ps = 0.f, pd = 0.f;
#pragma unroll
    for (int j = 0; j < 5; j++) {
        ps = fmaf(acc[j], as[j], ps);
        pd = fmaf(acc[j], ad[j], pd);
    }
    ps += __shfl_xor_sync(0xffffffffu, ps, 1);
    ps += __shfl_xor_sync(0xffffffffu, ps, 2);
    ps += __shfl_xor_sync(0xffffffffu, ps, 4);
    pd += __shfl_xor_sync(0xffffffffu, pd, 1);
    pd += __shfl_xor_sync(0xffffffffu, pd, 2);
    pd += __shfl_xor_sync(0xffffffffu, pd, 4);

    int row = row0 + rg;
    if (row < NN) {
#pragma unroll
        for (int j = 0; j < 5; j++)
            g_h2[(size_t)row * 40 + cg * 5 + j] = __float2half(acc[j]);
        if (cg == 0) {
            g_als[row] = ps;
            g_ald[row] = pd;
        }
    }
}

// ---- layer 2: single-pass agg (ELL, fp16 gather) + bias + log_softmax ---------
__global__ void __launch_bounds__(256)
k_agg2(const float* __restrict__ b2, float* __restrict__ out) {
    int warp = (blockIdx.x * blockDim.x + threadIdx.x) >> 5;
    int lane = threadIdx.x & 31;
    if (warp >= NN) return;
    int node = warp;
    int deg = g_deg[node];
    const int* rowp = &g_ell[(size_t)node * CAP];
    float aldn = g_ald[node];

    float acc0 = 0.f, acc1 = 0.f, den = 0.f;
    for (int base = 0; base < deg; base += 32) {
        int j = base + lane;
        int sj = (j < deg) ? rowp[j] : 0;
        float e = __ldg(&g_als[sj]) + aldn;
        e = (e >= 0.f) ? e : 0.2f * e;
        float al = (j < deg) ? __expf(e) : 0.f;
#pragma unroll
        for (int k8 = 0; k8 < 4; k8++) {
            if (base + 8 * k8 >= deg) break;
            int s[8];
            float w[8];
#pragma unroll
            for (int u = 0; u < 8; u++) {
                s[u] = __shfl_sync(0xffffffffu, sj, 8 * k8 + u);
                w[u] = __shfl_sync(0xffffffffu, al, 8 * k8 + u);
            }
            float h0[8], h1[8];
#pragma unroll
            for (int u = 0; u < 8; u++) {
                const __half* hr = &g_h2[(size_t)s[u] * 40];
                h0[u] = __half2float(hr[lane]);
                h1[u] = (lane < 8) ? __half2float(hr[32 + lane]) : 0.f;
            }
#pragma unroll
            for (int u = 0; u < 8; u++) {
                den += w[u];
                acc0 = fmaf(w[u], h0[u], acc0);
                acc1 = fmaf(w[u], h1[u], acc1);
            }
        }
    }
    float invd = 1.f / den;

    float v0 = fmaf(acc0, invd, __ldg(&b2[lane]));
    float v1 = (lane < 8) ? fmaf(acc1, invd, __ldg(&b2[32 + lane])) : -1e30f;
    float mx = fmaxf(v0, v1);
#pragma unroll
    for (int off = 16; off > 0; off >>= 1)
        mx = fmaxf(mx, __shfl_xor_sync(0xffffffffu, mx, off));
    float se = __expf(v0 - mx) + ((lane < 8) ? __expf(v1 - mx) : 0.f);
#pragma unroll
    for (int off = 16; off > 0; off >>= 1)
        se += __shfl_xor_sync(0xffffffffu, se, off);
    float lse = mx + __logf(se);

    out[(size_t)node * 40 + lane] = v0 - lse;
    if (lane < 8) out[(size_t)node * 40 + 32 + lane] = v1 - lse;
}

// ---------------- launch -------------------------------------------------------
extern "C" void kernel_launch(void* const* d_in, const int* in_sizes, int n_in,
                              void* d_out, int out_size) {
    const float* x   = (const float*)d_in[0];
    const void*  ei  = d_in[1];
    const float* W0  = (const float*)d_in[2];
    const float* as0 = (const float*)d_in[3];
    const float* ad0 = (const float*)d_in[4];
    const float* b0  = (const float*)d_in[5];
    const float* W1  = (const float*)d_in[6];
    const float* as1 = (const float*)d_in[7];
    const float* ad1 = (const float*)d_in[8];
    const float* b1  = (const float*)d_in[9];
    const float* W2  = (const float*)d_in[10];
    const float* as2 = (const float*)d_in[11];
    const float* ad2 = (const float*)d_in[12];
    const float* b2  = (const float*)d_in[13];
    float* out = (float*)d_out;

    static cudaStream_t s2 = nullptr;
    static cudaEvent_t evA = nullptr, evB = nullptr;
    if (s2 == nullptr) {
        cudaStreamCreateWithFlags(&s2, cudaStreamNonBlocking);
        cudaEventCreateWithFlags(&evA, cudaEventDisableTiming);
        cudaEventCreateWithFlags(&evB, cudaEventDisableTiming);
        cudaFuncSetAttribute(k_gemm_mma, cudaFuncAttributeMaxDynamicSharedMemorySize, SMH_TOT);
    }

    const int TC_BLKS  = (NN + 127) / 128;        // 391
    const int AGG_BLKS = (NN * 32 + 255) / 256;   // one warp per node

    // init (detect + deg zero) — the only adjacency prerequisites
    k_init<<<(NN + 511) / 512, 512>>>((const int*)ei);

    // fork: single-pass ELL build on s2, overlapped with W split + layer-0 GEMM
    cudaEventRecord(evA, 0);
    cudaStreamWaitEvent(s2, evA, 0);
    k_fill<<<(ETOT + 511) / 512, 512, 0, s2>>>(ei);
    cudaEventRecord(evB, s2);

    k_wsplit<<<(32768 + 511) / 512, 512>>>(W0, W1);
    k_gemm_mma<<<TC_BLKS, 512, SMH_TOT>>>(x, 0, 0, as0, ad0);

    // join: aggregation needs both adjacency and h
    cudaStreamWaitEvent(0, evB, 0);
    k_agg<<<AGG_BLKS, 256>>>(b0);

    // layer 1
    k_gemm_mma<<<TC_BLKS, 512, SMH_TOT>>>(nullptr, 1, 1, as1, ad1);
    k_agg<<<AGG_BLKS, 256>>>(b1);

    // layer 2
    k_gemm40<<<(NN + 31) / 32, 256>>>(W2, as2, ad2);
    k_agg2<<<AGG_BLKS, 256>>>(b2, out);
}

// round 14
// speedup vs baseline: 1.0084x; 1.0084x over previous
#include <cuda_runtime.h>
#include <cuda_bf16.h>
#include <cuda_fp16.h>
#include <math.h>
#include <cstdint>

#define NN   50000
#define EE0  800000
#define ETOT 850000
#define NH   4
#define SCAN_B 512
#define NB   ((NN + SCAN_B - 1) / SCAN_B)   // 98

// ---------------- scratch (device globals; no allocation allowed) -------------
__device__ __align__(16) __half g_feat[(size_t)NN * 128];  // inter-layer feats (fp16)
__device__ __align__(16) __half g_h01[(size_t)NN * 128];   // layers 0/1 h (fp16)
__device__ __align__(16) __half g_h2[(size_t)NN * 40];     // layer 2 h (fp16)
__device__ __align__(16) float g_als[NN * NH];
__device__ __align__(16) float g_ald[NN * NH];
__device__ __align__(16) __nv_bfloat16 g_Whi[2][16384];
__device__ __align__(16) __nv_bfloat16 g_Wlo[2][16384];
__device__ int g_deg[NN];
__device__ int g_row[NN + 1];
__device__ int g_cur[NN];
__device__ int g_bsum[NB];
__device__ int g_srcv[ETOT];
__device__ int g_is64;

// ---------------- small helpers -----------------------------------------------
#define MMA_BF16(d, a, b) \
    asm volatile("mma.sync.aligned.m16n8k16.row.col.f32.bf16.bf16.f32 " \
        "{%0,%1,%2,%3}, {%4,%5,%6,%7}, {%8,%9}, {%0,%1,%2,%3};" \
        : "+f"((d)[0]), "+f"((d)[1]), "+f"((d)[2]), "+f"((d)[3]) \
        : "r"((a)[0]), "r"((a)[1]), "r"((a)[2]), "r"((a)[3]), "r"((b)[0]), "r"((b)[1]))

__device__ __forceinline__ void split_bf16(float x, __nv_bfloat16& h, __nv_bfloat16& l) {
    h = __float2bfloat16(x);
    l = __float2bfloat16(x - __bfloat162float(h));
}
__device__ __forceinline__ uint32_t bfpair(__nv_bfloat16 a, __nv_bfloat16 b) {
    return (uint32_t)__bfloat16_as_ushort(a) | ((uint32_t)__bfloat16_as_ushort(b) << 16);
}

// ---------------- edge access --------------------------------------------------
__device__ __forceinline__ void get_edge(const void* ei, int e, int& s, int& d) {
    if (e >= EE0) { s = e - EE0; d = s; return; }
    if (g_is64) {
        const long long* p = (const long long*)ei;
        s = (int)p[e];
        d = (int)p[EE0 + e];
    } else {
        const int* p = (const int*)ei;
        s = p[e];
        d = p[EE0 + e];
    }
}
__device__ __forceinline__ int get_dst(const void* ei, int e) {
    if (e >= EE0) return e - EE0;
    if (g_is64) return (int)((const long long*)ei)[EE0 + e];
    return ((const int*)ei)[EE0 + e];
}

// ---------------- init: dtype detect + deg zero (CSR prerequisites only) -------
__global__ void k_init(const int* __restrict__ ei32) {
    int i = blockIdx.x * blockDim.x + threadIdx.x;
    if (blockIdx.x == 0) {
        __shared__ int zc;
        if (threadIdx.x == 0) zc = 0;
        __syncthreads();
        int z = 0;
        for (int k = threadIdx.x; k < 1024; k += blockDim.x)
            if (ei32[2 * k + 1] == 0) z++;
        atomicAdd(&zc, z);
        __syncthreads();
        if (threadIdx.x == 0) g_is64 = (zc > 512) ? 1 : 0;
    }
    if (i < NN) g_deg[i] = 0;
}

// ---------------- W split (needed only by GEMMs) -------------------------------
__global__ void k_wsplit(const float* __restrict__ W0, const float* __restrict__ W1) {
    int i = blockIdx.x * blockDim.x + threadIdx.x;
    if (i < 16384) {
        split_bf16(W0[i], g_Whi[0][i], g_Wlo[0][i]);
    } else if (i < 32768) {
        split_bf16(W1[i - 16384], g_Whi[1][i - 16384], g_Wlo[1][i - 16384]);
    }
}

// ---------------- CSR build ---------------------------------------------------
__global__ void k_count(const void* __restrict__ ei) {
    int e = blockIdx.x * blockDim.x + threadIdx.x;
    if (e >= ETOT) return;
    atomicAdd(&g_deg[get_dst(ei, e)], 1);
}

__global__ void k_scan1() {
    __shared__ int sm[SCAN_B];
    int t = threadIdx.x;
    int idx = blockIdx.x * SCAN_B + t;
    int v = (idx < NN) ? g_deg[idx] : 0;
    sm[t] = v;
    __syncthreads();
#pragma unroll
    for (int off = 1; off < SCAN_B; off <<= 1) {
        int p = (t >= off) ? sm[t - off] : 0;
        __syncthreads();
        sm[t] += p;
        __syncthreads();
    }
    if (idx < NN) g_row[idx] = sm[t] - v;
    if (t == SCAN_B - 1) g_bsum[blockIdx.x] = sm[t];
}

__global__ void k_scan23() {
    __shared__ int sm[128];
    int t = threadIdx.x;
    int b = blockIdx.x;
    if (t < 128) {
        sm[t] = (t < NB) ? g_bsum[t] : 0;
    }
    __syncthreads();
#pragma unroll
    for (int off = 1; off < 128; off <<= 1) {
        int p = 0;
        if (t < 128 && t >= off) p = sm[t - off];
        __syncthreads();
        if (t < 128) sm[t] += p;
        __syncthreads();
    }
    int boff = (b > 0) ? sm[b - 1] : 0;
    int idx = b * SCAN_B + t;
    if (idx < NN) {
        int r = g_row[idx] + boff;
        g_row[idx] = r;
        g_cur[idx] = r;
    }
    if (idx == 0) g_row[NN] = ETOT;
}

__global__ void k_fill(const void* __restrict__ ei) {
    int e = blockIdx.x * blockDim.x + threadIdx.x;
    if (e >= ETOT) return;
    int s, d;
    get_edge(ei, e, s, d);
    int pos = atomicAdd(&g_cur[d], 1);
    g_srcv[pos] = s;
}

// ======= bf16x3 GEMM via mma.sync, 64x64 tiles, 256 thr, 3 blocks/SM ==========
// smem layout: AS[128]f @0, AD[128]f @512, Xhi/Xlo[64][136] bf16, Whi/Wlo[64][136]
#define SM2_XHI 1024
#define SM2_XLO (SM2_XHI + 64 * 136 * 2)
#define SM2_WHI (SM2_XLO + 64 * 136 * 2)
#define SM2_WLO (SM2_WHI + 64 * 136 * 2)
#define SM2_TOT (SM2_WLO + 64 * 136 * 2)   // 70656
#define ROW_TILES ((NN + 63) / 64)          // 782

__global__ void __launch_bounds__(256, 3)
k_gemm_mma(const float* __restrict__ xin, int use_gfeat, int widx,
           const float* __restrict__ a_src, const float* __restrict__ a_dst) {
    extern __shared__ char smem[];
    float* AS = (float*)(smem);
    float* AD = (float*)(smem + 512);
    __nv_bfloat16* Xhi = (__nv_bfloat16*)(smem + SM2_XHI);
    __nv_bfloat16* Xlo = (__nv_bfloat16*)(smem + SM2_XLO);
    __nv_bfloat16* Whi = (__nv_bfloat16*)(smem + SM2_WHI);
    __nv_bfloat16* Wlo = (__nv_bfloat16*)(smem + SM2_WLO);
    int tid = threadIdx.x;
    int row0 = (blockIdx.x >> 1) * 64;      // 64-row tile
    int c0   = (blockIdx.x & 1) * 64;       // 64-col half

    if (tid < 128) {
        AS[tid] = a_src[tid];
        AD[tid] = a_dst[tid];
    }
    // stage X (64 rows, full K=128): fp32 input or fp16 g_feat -> bf16 hi/lo
    for (int idx = tid; idx < 64 * 32; idx += 256) {
        int r = idx >> 5, c4 = (idx & 31) * 4;
        int row = row0 + r;
        float4 v = make_float4(0.f, 0.f, 0.f, 0.f);
        if (row < NN) {
            if (use_gfeat) {
                uint2 hv = *(const uint2*)(g_feat + (size_t)row * 128 + c4);
                float2 fa = __half22float2(*reinterpret_cast<__half2*>(&hv.x));
                float2 fb = __half22float2(*reinterpret_cast<__half2*>(&hv.y));
                v = make_float4(fa.x, fa.y, fb.x, fb.y);
            } else {
                v = *(const float4*)&xin[(size_t)row * 128 + c4];
            }
        }
        __nv_bfloat16 h0, h1, h2, h3, l0, l1, l2, l3;
        split_bf16(v.x, h0, l0);
        split_bf16(v.y, h1, l1);
        split_bf16(v.z, h2, l2);
        split_bf16(v.w, h3, l3);
        uint32_t* dh = (uint32_t*)(Xhi + r * 136 + c4);
        uint32_t* dl = (uint32_t*)(Xlo + r * 136 + c4);
        dh[0] = bfpair(h0, h1);
        dh[1] = bfpair(h2, h3);
        dl[0] = bfpair(l0, l1);
        dl[1] = bfpair(l2, l3);
    }
    // stage W half (64 N-rows starting at c0), pre-split in global
    {
        const __nv_bfloat16* whi = g_Whi[widx] + (size_t)c0 * 128;
        const __nv_bfloat16* wlo = g_Wlo[widx] + (size_t)c0 * 128;
        for (int idx = tid; idx < 1024; idx += 256) {
            int n = idx >> 4, kc = (idx & 15) * 8;
            *(uint4*)(Whi + n * 136 + kc) = *(const uint4*)(whi + n * 128 + kc);
            *(uint4*)(Wlo + n * 136 + kc) = *(const uint4*)(wlo + n * 128 + kc);
        }
    }
    __syncthreads();

    int w = tid >> 5;         // 8 warps
    int lane = tid & 31;
    int g = lane >> 2;        // 0..7
    int tig = lane & 3;       // 0..3
    int rw = (w & 3) * 16;    // row group: 4 groups of 16
    int cn = (w >> 2) * 32;   // col group within half: 0 or 32

    float acc[4][4];
#pragma unroll
    for (int i = 0; i < 4; i++)
#pragma unroll
        for (int j = 0; j < 4; j++) acc[i][j] = 0.f;

#pragma unroll
    for (int kt = 0; kt < 8; kt++) {
        int kk = kt * 16 + 2 * tig;
        int rA = rw + g, rB = rA + 8;
        uint32_t ahi[4], alo[4];
        ahi[0] = *(const uint32_t*)(Xhi + rA * 136 + kk);
        ahi[1] = *(const uint32_t*)(Xhi + rB * 136 + kk);
        ahi[2] = *(const uint32_t*)(Xhi + rA * 136 + kk + 8);
        ahi[3] = *(const uint32_t*)(Xhi + rB * 136 + kk + 8);
        alo[0] = *(const uint32_t*)(Xlo + rA * 136 + kk);
        alo[1] = *(const uint32_t*)(Xlo + rB * 136 + kk);
        alo[2] = *(const uint32_t*)(Xlo + rA * 136 + kk + 8);
        alo[3] = *(const uint32_t*)(Xlo + rB * 136 + kk + 8);
#pragma unroll
        for (int nt = 0; nt < 4; nt++) {
            int nc = cn + nt * 8 + g;       // local W row (0..63)
            uint32_t bhi[2], blo[2];
            bhi[0] = *(const uint32_t*)(Whi + nc * 136 + kk);
            bhi[1] = *(const uint32_t*)(Whi + nc * 136 + kk + 8);
            blo[0] = *(const uint32_t*)(Wlo + nc * 136 + kk);
            blo[1] = *(const uint32_t*)(Wlo + nc * 136 + kk + 8);
            MMA_BF16(acc[nt], ahi, bhi);
            MMA_BF16(acc[nt], ahi, blo);
            MMA_BF16(acc[nt], alo, bhi);
        }
    }

    // epilogue: warp covers exactly one head (32 cols). rows rw+g, rw+g+8.
    int rowA = row0 + rw + g;
    int rowB = rowA + 8;
    int head = (c0 + cn) >> 5;
    float psA = 0.f, psB = 0.f, pdA = 0.f, pdB = 0.f;
#pragma unroll
    for (int nt = 0; nt < 4; nt++) {
        int gc = c0 + cn + nt * 8 + 2 * tig;   // global col
        float a0 = AS[gc], a1 = AS[gc + 1];
        float d0 = AD[gc], d1 = AD[gc + 1];
        psA += acc[nt][0] * a0 + acc[nt][1] * a1;
        psB += acc[nt][2] * a0 + acc[nt][3] * a1;
        pdA += acc[nt][0] * d0 + acc[nt][1] * d1;
        pdB += acc[nt][2] * d0 + acc[nt][3] * d1;
        if (rowA < NN)
            *(__half2*)&g_h01[(size_t)rowA * 128 + gc] = __floats2half2_rn(acc[nt][0], acc[nt][1]);
        if (rowB < NN)
            *(__half2*)&g_h01[(size_t)rowB * 128 + gc] = __floats2half2_rn(acc[nt][2], acc[nt][3]);
    }
    psA += __shfl_xor_sync(0xffffffffu, psA, 1);
    psA += __shfl_xor_sync(0xffffffffu, psA, 2);
    psB += __shfl_xor_sync(0xffffffffu, psB, 1);
    psB += __shfl_xor_sync(0xffffffffu, psB, 2);
    pdA += __shfl_xor_sync(0xffffffffu, pdA, 1);
    pdA += __shfl_xor_sync(0xffffffffu, pdA, 2);
    pdB += __shfl_xor_sync(0xffffffffu, pdB, 1);
    pdB += __shfl_xor_sync(0xffffffffu, pdB, 2);
    if (tig == 0) {
        if (rowA < NN) {
            g_als[rowA * 4 + head] = psA;
            g_ald[rowA * 4 + head] = pdA;
        }
        if (rowB < NN) {
            g_als[rowB * 4 + head] = psB;
            g_ald[rowB * 4 + head] = pdB;
        }
    }
}

// --- single-pass softmax + aggregation, fp16 gather, unrolled-8 (layers 0/1) ---
__global__ void __launch_bounds__(256)
k_agg(const float* __restrict__ bias) {
    int warp = (blockIdx.x * blockDim.x + threadIdx.x) >> 5;
    int lane = threadIdx.x & 31;
    if (warp >= NN) return;
    int node = warp;
    int start = g_row[node], end = g_row[node + 1];

    int head = lane >> 3;
    int sub = lane & 7;
    float aldh = g_ald[node * 4 + head];
    int c4 = lane * 4;
    float4 acc = make_float4(0.f, 0.f, 0.f, 0.f);
    float den = 0.f;

    for (int base = start; base < end; base += 32) {
        int j = base + lane;
        int sj = (j < end) ? g_srcv[j] : 0;
        float er[4];
#pragma unroll
        for (int k = 0; k < 4; k++) {
            int s2 = __shfl_sync(0xffffffffu, sj, sub + 8 * k);
            float e = __ldg(&g_als[s2 * 4 + head]) + aldh;
            e = (e >= 0.f) ? e : 0.2f * e;
            er[k] = (base + sub + 8 * k < end) ? __expf(e) : 0.f;
        }
#pragma unroll
        for (int k8 = 0; k8 < 4; k8++) {
            if (base + 8 * k8 >= end) break;
            float ek = er[k8];
            int s[8];
            float w[8];
#pragma unroll
            for (int u = 0; u < 8; u++) {
                s[u] = __shfl_sync(0xffffffffu, sj, 8 * k8 + u);
                w[u] = __shfl_sync(0xffffffffu, ek, (head << 3) | u);
            }
            uint2 hv[8];
#pragma unroll
            for (int u = 0; u < 8; u++)
                hv[u] = *(const uint2*)(g_h01 + (size_t)s[u] * 128 + c4);
#pragma unroll
            for (int u = 0; u < 8; u++) {
                float2 fa = __half22float2(*reinterpret_cast<__half2*>(&hv[u].x));
                float2 fb = __half22float2(*reinterpret_cast<__half2*>(&hv[u].y));
                den += w[u];
                acc.x = fmaf(w[u], fa.x, acc.x);
                acc.y = fmaf(w[u], fa.y, acc.y);
                acc.z = fmaf(w[u], fb.x, acc.z);
                acc.w = fmaf(w[u], fb.y, acc.w);
            }
        }
    }

    float invd = 1.f / den;
    float4 bv = *(const float4*)&bias[c4];
    float r0 = fmaf(acc.x, invd, bv.x);
    float r1 = fmaf(acc.y, invd, bv.y);
    float r2 = fmaf(acc.z, invd, bv.z);
    float r3 = fmaf(acc.w, invd, bv.w);
    r0 = (r0 > 0.f) ? r0 : expm1f(r0);
    r1 = (r1 > 0.f) ? r1 : expm1f(r1);
    r2 = (r2 > 0.f) ? r2 : expm1f(r2);
    r3 = (r3 > 0.f) ? r3 : expm1f(r3);
    uint2 o;
    *reinterpret_cast<__half2*>(&o.x) = __floats2half2_rn(r0, r1);
    *reinterpret_cast<__half2*>(&o.y) = __floats2half2_rn(r2, r3);
    *(uint2*)(g_feat + (size_t)node * 128 + c4) = o;
}

// ---------------- layer 2: GEMM (Nout=40) + fused attention dots ---------------
__global__ void __launch_bounds__(256)
k_gemm40(const float* __restrict__ W2,
         const float* __restrict__ a_src2, const float* __restrict__ a_dst2) {
    __shared__ float Wt[128 * 44];
    __shared__ float Xs[32 * 128];
    int t = threadIdx.x;
    int row0 = blockIdx.x * 32;

    for (int idx = t; idx < 40 * 128; idx += 256) {
        int c = idx >> 7, k = idx & 127;
        Wt[k * 44 + c] = W2[idx];
    }
    for (int idx = t; idx < 32 * 32; idx += 256) {
        int r = idx >> 5, c4 = (idx & 31) * 4;
        int row = row0 + r;
        float4 v = make_float4(0.f, 0.f, 0.f, 0.f);
        if (row < NN) {
            uint2 hv = *(const uint2*)(g_feat + (size_t)row * 128 + c4);
            float2 fa = __half22float2(*reinterpret_cast<__half2*>(&hv.x));
            float2 fb = __half22float2(*reinterpret_cast<__half2*>(&hv.y));
            v = make_float4(fa.x, fa.y, fb.x, fb.y);
        }
        *(float4*)&Xs[r * 128 + c4] = v;
    }

    int cg = t & 7;
    int rg = t >> 3;
    float as[5], ad[5];
#pragma unroll
    for (int j = 0; j < 5; j++) {
        as[j] = __ldg(&a_src2[cg * 5 + j]);
        ad[j] = __ldg(&a_dst2[cg * 5 + j]);
    }
    __syncthreads();

    float acc[5] = {0.f, 0.f, 0.f, 0.f, 0.f};
#pragma unroll 4
    for (int k = 0; k < 128; k++) {
        float a = Xs[rg * 128 + k];
#pragma unroll
        for (int j = 0; j < 5; j++)
            acc[j] = fmaf(a, Wt[k * 44 + cg * 5 + j], acc[j]);
    }

    float ps = 0.f, pd = 0.f;
#pragma unroll
    for (int j = 0; j < 5; j++) {
        ps = fmaf(acc[j], as[j], ps);
        pd = fmaf(acc[j], ad[j], pd);
    }
    ps += __shfl_xor_sync(0xffffffffu, ps, 1);
    ps += __shfl_xor_sync(0xffffffffu, ps, 2);
    ps += __shfl_xor_sync(0xffffffffu, ps, 4);
    pd += __shfl_xor_sync(0xffffffffu, pd, 1);
    pd += __shfl_xor_sync(0xffffffffu, pd, 2);
    pd += __shfl_xor_sync(0xffffffffu, pd, 4);

    int row = row0 + rg;
    if (row < NN) {
#pragma unroll
        for (int j = 0; j < 5; j++)
            g_h2[(size_t)row * 40 + cg * 5 + j] = __float2half(acc[j]);
        if (cg == 0) {
            g_als[row] = ps;
            g_ald[row] = pd;
        }
    }
}

// ---- layer 2: single-pass agg (fp16 gather) + bias + log_softmax fused --------
__global__ void __launch_bounds__(256)
k_agg2(const float* __restrict__ b2, float* __restrict__ out) {
    int warp = (blockIdx.x * blockDim.x + threadIdx.x) >> 5;
    int lane = threadIdx.x & 31;
    if (warp >= NN) return;
    int node = warp;
    int start = g_row[node], end = g_row[node + 1];
    float aldn = g_ald[node];

    float acc0 = 0.f, acc1 = 0.f, den = 0.f;
    for (int base = start; base < end; base += 32) {
        int j = base + lane;
        int sj = (j < end) ? g_srcv[j] : 0;
        float e = __ldg(&g_als[sj]) + aldn;
        e = (e >= 0.f) ? e : 0.2f * e;
        float al = (j < end) ? __expf(e) : 0.f;
#pragma unroll
        for (int k8 = 0; k8 < 4; k8++) {
            if (base + 8 * k8 >= end) break;
            int s[8];
            float w[8];
#pragma unroll
            for (int u = 0; u < 8; u++) {
                s[u] = __shfl_sync(0xffffffffu, sj, 8 * k8 + u);
                w[u] = __shfl_sync(0xffffffffu, al, 8 * k8 + u);
            }
            float h0[8], h1[8];
#pragma unroll
            for (int u = 0; u < 8; u++) {
                const __half* hr = &g_h2[(size_t)s[u] * 40];
                h0[u] = __half2float(hr[lane]);
                h1[u] = (lane < 8) ? __half2float(hr[32 + lane]) : 0.f;
            }
#pragma unroll
            for (int u = 0; u < 8; u++) {
                den += w[u];
                acc0 = fmaf(w[u], h0[u], acc0);
                acc1 = fmaf(w[u], h1[u], acc1);
            }
        }
    }
    float invd = 1.f / den;

    float v0 = fmaf(acc0, invd, __ldg(&b2[lane]));
    float v1 = (lane < 8) ? fmaf(acc1, invd, __ldg(&b2[32 + lane])) : -1e30f;
    float mx = fmaxf(v0, v1);
#pragma unroll
    for (int off = 16; off > 0; off >>= 1)
        mx = fmaxf(mx, __shfl_xor_sync(0xffffffffu, mx, off));
    float se = __expf(v0 - mx) + ((lane < 8) ? __expf(v1 - mx) : 0.f);
#pragma unroll
    for (int off = 16; off > 0; off >>= 1)
        se += __shfl_xor_sync(0xffffffffu, se, off);
    float lse = mx + __logf(se);

    out[(size_t)node * 40 + lane] = v0 - lse;
    if (lane < 8) out[(size_t)node * 40 + 32 + lane] = v1 - lse;
}

// ---------------- launch -------------------------------------------------------
extern "C" void kernel_launch(void* const* d_in, const int* in_sizes, int n_in,
                              void* d_out, int out_size) {
    const float* x   = (const float*)d_in[0];
    const void*  ei  = d_in[1];
    const float* W0  = (const float*)d_in[2];
    const float* as0 = (const float*)d_in[3];
    const float* ad0 = (const float*)d_in[4];
    const float* b0  = (const float*)d_in[5];
    const float* W1  = (const float*)d_in[6];
    const float* as1 = (const float*)d_in[7];
    const float* ad1 = (const float*)d_in[8];
    const float* b1  = (const float*)d_in[9];
    const float* W2  = (const float*)d_in[10];
    const float* as2 = (const float*)d_in[11];
    const float* ad2 = (const float*)d_in[12];
    const float* b2  = (const float*)d_in[13];
    float* out = (float*)d_out;

    static cudaStream_t s2 = nullptr;
    static cudaEvent_t evA = nullptr, evB = nullptr;
    if (s2 == nullptr) {
        cudaStreamCreateWithFlags(&s2, cudaStreamNonBlocking);
        cudaEventCreateWithFlags(&evA, cudaEventDisableTiming);
        cudaEventCreateWithFlags(&evB, cudaEventDisableTiming);
        cudaFuncSetAttribute(k_gemm_mma, cudaFuncAttributeMaxDynamicSharedMemorySize, SM2_TOT);
    }

    const int TC_BLKS  = ROW_TILES * 2;           // 1564 (64-row x 64-col tiles)
    const int AGG_BLKS = (NN * 32 + 255) / 256;   // one warp per node

    // init (detect + deg zero) — the only CSR prerequisites
    k_init<<<(NN + 511) / 512, 512>>>((const int*)ei);

    // fork: CSR build on s2, overlapped with W split + layer-0 GEMM on main
    cudaEventRecord(evA, 0);
    cudaStreamWaitEvent(s2, evA, 0);
    k_count<<<(ETOT + 511) / 512, 512, 0, s2>>>(ei);
    k_scan1<<<NB, SCAN_B, 0, s2>>>();
    k_scan23<<<NB, SCAN_B, 0, s2>>>();
    k_fill<<<(ETOT + 511) / 512, 512, 0, s2>>>(ei);
    cudaEventRecord(evB, s2);

    k_wsplit<<<(32768 + 511) / 512, 512>>>(W0, W1);
    k_gemm_mma<<<TC_BLKS, 256, SM2_TOT>>>(x, 0, 0, as0, ad0);

    // join: aggregation needs both CSR and h
    cudaStreamWaitEvent(0, evB, 0);
    k_agg<<<AGG_BLKS, 256>>>(b0);

    // layer 1
    k_gemm_mma<<<TC_BLKS, 256, SM2_TOT>>>(nullptr, 1, 1, as1, ad1);
    k_agg<<<AGG_BLKS, 256>>>(b1);

    // layer 2
    k_gemm40<<<(NN + 31) / 32, 256>>>(W2, as2, ad2);
    k_agg2<<<AGG_BLKS, 256>>>(b2, out);
}

// round 15
// speedup vs baseline: 1.0415x; 1.0328x over previous
#include <cuda_runtime.h>
#include <cuda_bf16.h>
#include <cuda_fp16.h>
#include <math.h>
#include <cstdint>

#define NN   50000
#define EE0  800000
#define ETOT 850000
#define NH   4
#define SCAN_B 512
#define NB   ((NN + SCAN_B - 1) / SCAN_B)   // 98

// ---------------- scratch (device globals; no allocation allowed) -------------
__device__ __align__(16) __half g_feat[(size_t)NN * 128];  // inter-layer feats (fp16)
__device__ __align__(16) __half g_h01[(size_t)NN * 128];   // layers 0/1 h (fp16)
__device__ __align__(16) __half g_h2[(size_t)NN * 40];     // layer 2 h (fp16)
__device__ __align__(16) float g_als[NN * NH];
__device__ __align__(16) float g_ald[NN * NH];
__device__ __align__(16) __nv_bfloat16 g_Whi[2][16384];
__device__ __align__(16) __nv_bfloat16 g_Wlo[2][16384];
__device__ int g_deg[NN];
__device__ int g_row[NN + 1];
__device__ int g_cur[NN];
__device__ int g_bsum[NB];
__device__ int g_srcv[ETOT];
__device__ int g_is64;

// ---------------- small helpers -----------------------------------------------
#define MMA_BF16(d, a, b) \
    asm volatile("mma.sync.aligned.m16n8k16.row.col.f32.bf16.bf16.f32 " \
        "{%0,%1,%2,%3}, {%4,%5,%6,%7}, {%8,%9}, {%0,%1,%2,%3};" \
        : "+f"((d)[0]), "+f"((d)[1]), "+f"((d)[2]), "+f"((d)[3]) \
        : "r"((a)[0]), "r"((a)[1]), "r"((a)[2]), "r"((a)[3]), "r"((b)[0]), "r"((b)[1]))

#define LDSM_X4(r0, r1, r2, r3, addr) \
    asm volatile("ldmatrix.sync.aligned.m8n8.x4.shared.b16 {%0,%1,%2,%3}, [%4];" \
        : "=r"(r0), "=r"(r1), "=r"(r2), "=r"(r3) : "r"(addr))

#define LDSM_X2(r0, r1, addr) \
    asm volatile("ldmatrix.sync.aligned.m8n8.x2.shared.b16 {%0,%1}, [%2];" \
        : "=r"(r0), "=r"(r1) : "r"(addr))

__device__ __forceinline__ uint32_t sm_u32(const void* p) {
    return (uint32_t)__cvta_generic_to_shared(p);
}
__device__ __forceinline__ void split_bf16(float x, __nv_bfloat16& h, __nv_bfloat16& l) {
    h = __float2bfloat16(x);
    l = __float2bfloat16(x - __bfloat162float(h));
}
__device__ __forceinline__ uint32_t bfpair(__nv_bfloat16 a, __nv_bfloat16 b) {
    return (uint32_t)__bfloat16_as_ushort(a) | ((uint32_t)__bfloat16_as_ushort(b) << 16);
}

// ---------------- edge access --------------------------------------------------
__device__ __forceinline__ void get_edge(const void* ei, int e, int& s, int& d) {
    if (e >= EE0) { s = e - EE0; d = s; return; }
    if (g_is64) {
        const long long* p = (const long long*)ei;
        s = (int)p[e];
        d = (int)p[EE0 + e];
    } else {
        const int* p = (const int*)ei;
        s = p[e];
        d = p[EE0 + e];
    }
}
__device__ __forceinline__ int get_dst(const void* ei, int e) {
    if (e >= EE0) return e - EE0;
    if (g_is64) return (int)((const long long*)ei)[EE0 + e];
    return ((const int*)ei)[EE0 + e];
}

// ---------------- init: dtype detect + deg zero (CSR prerequisites only) -------
__global__ void k_init(const int* __restrict__ ei32) {
    int i = blockIdx.x * blockDim.x + threadIdx.x;
    if (blockIdx.x == 0) {
        __shared__ int zc;
        if (threadIdx.x == 0) zc = 0;
        __syncthreads();
        int z = 0;
        for (int k = threadIdx.x; k < 1024; k += blockDim.x)
            if (ei32[2 * k + 1] == 0) z++;
        atomicAdd(&zc, z);
        __syncthreads();
        if (threadIdx.x == 0) g_is64 = (zc > 512) ? 1 : 0;
    }
    if (i < NN) g_deg[i] = 0;
}

// ---------------- W split (needed only by GEMMs) -------------------------------
__global__ void k_wsplit(const float* __restrict__ W0, const float* __restrict__ W1) {
    int i = blockIdx.x * blockDim.x + threadIdx.x;
    if (i < 16384) {
        split_bf16(W0[i], g_Whi[0][i], g_Wlo[0][i]);
    } else if (i < 32768) {
        split_bf16(W1[i - 16384], g_Whi[1][i - 16384], g_Wlo[1][i - 16384]);
    }
}

// ---------------- CSR build ---------------------------------------------------
__global__ void k_count(const void* __restrict__ ei) {
    int e = blockIdx.x * blockDim.x + threadIdx.x;
    if (e >= ETOT) return;
    atomicAdd(&g_deg[get_dst(ei, e)], 1);
}

__global__ void k_scan1() {
    __shared__ int sm[SCAN_B];
    int t = threadIdx.x;
    int idx = blockIdx.x * SCAN_B + t;
    int v = (idx < NN) ? g_deg[idx] : 0;
    sm[t] = v;
    __syncthreads();
#pragma unroll
    for (int off = 1; off < SCAN_B; off <<= 1) {
        int p = (t >= off) ? sm[t - off] : 0;
        __syncthreads();
        sm[t] += p;
        __syncthreads();
    }
    if (idx < NN) g_row[idx] = sm[t] - v;
    if (t == SCAN_B - 1) g_bsum[blockIdx.x] = sm[t];
}

__global__ void k_scan23() {
    __shared__ int sm[128];
    int t = threadIdx.x;
    int b = blockIdx.x;
    if (t < 128) {
        sm[t] = (t < NB) ? g_bsum[t] : 0;
    }
    __syncthreads();
#pragma unroll
    for (int off = 1; off < 128; off <<= 1) {
        int p = 0;
        if (t < 128 && t >= off) p = sm[t - off];
        __syncthreads();
        if (t < 128) sm[t] += p;
        __syncthreads();
    }
    int boff = (b > 0) ? sm[b - 1] : 0;
    int idx = b * SCAN_B + t;
    if (idx < NN) {
        int r = g_row[idx] + boff;
        g_row[idx] = r;
        g_cur[idx] = r;
    }
    if (idx == 0) g_row[NN] = ETOT;
}

__global__ void k_fill(const void* __restrict__ ei) {
    int e = blockIdx.x * blockDim.x + threadIdx.x;
    if (e >= ETOT) return;
    int s, d;
    get_edge(ei, e, s, d);
    int pos = atomicAdd(&g_cur[d], 1);
    g_srcv[pos] = s;
}

// ======= bf16x3 GEMM via mma.sync + ldmatrix, 128x128 tile, fused att dots ====
#define SMH_XHI 1024
#define SMH_XLO (SMH_XHI + 128 * 136 * 2)
#define SMH_WHI (SMH_XLO + 128 * 136 * 2)
#define SMH_WLO (SMH_WHI + 128 * 136 * 2)
#define SMH_TOT (SMH_WLO + 128 * 136 * 2)   // 140288

__global__ void __launch_bounds__(512, 1)
k_gemm_mma(const float* __restrict__ xin, int use_gfeat, int widx,
           const float* __restrict__ a_src, const float* __restrict__ a_dst) {
    extern __shared__ char smem[];
    float* AS = (float*)(smem);
    float* AD = (float*)(smem + 512);
    __nv_bfloat16* Xhi = (__nv_bfloat16*)(smem + SMH_XHI);
    __nv_bfloat16* Xlo = (__nv_bfloat16*)(smem + SMH_XLO);
    __nv_bfloat16* Whi = (__nv_bfloat16*)(smem + SMH_WHI);
    __nv_bfloat16* Wlo = (__nv_bfloat16*)(smem + SMH_WLO);
    int tid = threadIdx.x;
    int row0 = blockIdx.x * 128;

    if (tid < 128) {
        AS[tid] = a_src[tid];
        AD[tid] = a_dst[tid];
    }
    // stage X: (fp32 input | fp16 g_feat) -> bf16 hi/lo in separate arrays
    for (int idx = tid; idx < 128 * 32; idx += 512) {
        int r = idx >> 5, c4 = (idx & 31) * 4;
        int row = row0 + r;
        float4 v = make_float4(0.f, 0.f, 0.f, 0.f);
        if (row < NN) {
            if (use_gfeat) {
                uint2 hv = *(const uint2*)(g_feat + (size_t)row * 128 + c4);
                float2 fa = __half22float2(*reinterpret_cast<__half2*>(&hv.x));
                float2 fb = __half22float2(*reinterpret_cast<__half2*>(&hv.y));
                v = make_float4(fa.x, fa.y, fb.x, fb.y);
            } else {
                v = *(const float4*)&xin[(size_t)row * 128 + c4];
            }
        }
        __nv_bfloat16 h0, h1, h2, h3, l0, l1, l2, l3;
        split_bf16(v.x, h0, l0);
        split_bf16(v.y, h1, l1);
        split_bf16(v.z, h2, l2);
        split_bf16(v.w, h3, l3);
        uint32_t* dh = (uint32_t*)(Xhi + r * 136 + c4);
        uint32_t* dl = (uint32_t*)(Xlo + r * 136 + c4);
        dh[0] = bfpair(h0, h1);
        dh[1] = bfpair(h2, h3);
        dl[0] = bfpair(l0, l1);
        dl[1] = bfpair(l2, l3);
    }
    {
        const __nv_bfloat16* whi = g_Whi[widx];
        const __nv_bfloat16* wlo = g_Wlo[widx];
        for (int idx = tid; idx < 2048; idx += 512) {
            int n = idx >> 4, kc = (idx & 15) * 8;
            *(uint4*)(Whi + n * 136 + kc) = *(const uint4*)(whi + n * 128 + kc);
            *(uint4*)(Wlo + n * 136 + kc) = *(const uint4*)(wlo + n * 128 + kc);
        }
    }
    __syncthreads();

    int w = tid >> 5;
    int lane = tid & 31;
    int g = lane >> 2;
    int tig = lane & 3;
    int rw = (w & 7) * 16;    // warp row base
    int cw = (w >> 3) * 64;   // warp col base (0 or 64)

    // ldmatrix per-lane addresses (bytes into shared space)
    // A x4: lane -> row rw + (lane&15), k-col ((lane>>4)*8)
    uint32_t aoffH = sm_u32(Xhi + (rw + (lane & 15)) * 136 + ((lane >> 4) << 3));
    uint32_t aoffL = sm_u32(Xlo + (rw + (lane & 15)) * 136 + ((lane >> 4) << 3));
    // B x2: lane(0..15) -> n-row cw + (lane&7), k-col ((lane>>3)&1)*8
    uint32_t boffH = sm_u32(Whi + (cw + (lane & 7)) * 136 + (((lane >> 3) & 1) << 3));
    uint32_t boffL = sm_u32(Wlo + (cw + (lane & 7)) * 136 + (((lane >> 3) & 1) << 3));

    float acc[8][4];
#pragma unroll
    for (int i = 0; i < 8; i++)
#pragma unroll
        for (int j = 0; j < 4; j++) acc[i][j] = 0.f;

#pragma unroll
    for (int kt = 0; kt < 8; kt++) {
        uint32_t ka = (uint32_t)kt * 32;   // 16 bf16 = 32 bytes per k-step
        uint32_t ahi[4], alo[4];
        LDSM_X4(ahi[0], ahi[1], ahi[2], ahi[3], aoffH + ka);
        LDSM_X4(alo[0], alo[1], alo[2], alo[3], aoffL + ka);
#pragma unroll
        for (int nt = 0; nt < 8; nt++) {
            uint32_t nb = (uint32_t)nt * (8 * 136 * 2);  // 8 n-rows per frag
            uint32_t bhi[2], blo[2];
            LDSM_X2(bhi[0], bhi[1], boffH + nb + ka);
            LDSM_X2(blo[0], blo[1], boffL + nb + ka);
            MMA_BF16(acc[nt], ahi, bhi);
            MMA_BF16(acc[nt], ahi, blo);
            MMA_BF16(acc[nt], alo, bhi);
        }
    }

    int rowA = row0 + rw + g;
    int rowB = rowA + 8;
    int h0 = (w >> 3) * 2;
    float ps0[2] = {0.f, 0.f}, ps1[2] = {0.f, 0.f};
    float pd0[2] = {0.f, 0.f}, pd1[2] = {0.f, 0.f};
#pragma unroll
    for (int nt = 0; nt < 8; nt++) {
        int h = nt >> 2;
        int c = cw + nt * 8 + 2 * tig;
        float a0 = AS[c], a1 = AS[c + 1];
        float d0 = AD[c], d1 = AD[c + 1];
        ps0[h] += acc[nt][0] * a0 + acc[nt][1] * a1;
        ps1[h] += acc[nt][2] * a0 + acc[nt][3] * a1;
        pd0[h] += acc[nt][0] * d0 + acc[nt][1] * d1;
        pd1[h] += acc[nt][2] * d0 + acc[nt][3] * d1;
        if (rowA < NN)
            *(__half2*)&g_h01[(size_t)rowA * 128 + c] = __floats2half2_rn(acc[nt][0], acc[nt][1]);
        if (rowB < NN)
            *(__half2*)&g_h01[(size_t)rowB * 128 + c] = __floats2half2_rn(acc[nt][2], acc[nt][3]);
    }
#pragma unroll
    for (int h = 0; h < 2; h++) {
        ps0[h] += __shfl_xor_sync(0xffffffffu, ps0[h], 1);
        ps0[h] += __shfl_xor_sync(0xffffffffu, ps0[h], 2);
        ps1[h] += __shfl_xor_sync(0xffffffffu, ps1[h], 1);
        ps1[h] += __shfl_xor_sync(0xffffffffu, ps1[h], 2);
        pd0[h] += __shfl_xor_sync(0xffffffffu, pd0[h], 1);
        pd0[h] += __shfl_xor_sync(0xffffffffu, pd0[h], 2);
        pd1[h] += __shfl_xor_sync(0xffffffffu, pd1[h], 1);
        pd1[h] += __shfl_xor_sync(0xffffffffu, pd1[h], 2);
    }
    if (tig == 0) {
#pragma unroll
        for (int h = 0; h < 2; h++) {
            if (rowA < NN) {
                g_als[rowA * 4 + h0 + h] = ps0[h];
                g_ald[rowA * 4 + h0 + h] = pd0[h];
            }
            if (rowB < NN) {
                g_als[rowB * 4 + h0 + h] = ps1[h];
                g_ald[rowB * 4 + h0 + h] = pd1[h];
            }
        }
    }
}

// --- single-pass softmax + aggregation, fp16 gather, unrolled-8 (layers 0/1) ---
__global__ void __launch_bounds__(256)
k_agg(const float* __restrict__ bias) {
    int warp = (blockIdx.x * blockDim.x + threadIdx.x) >> 5;
    int lane = threadIdx.x & 31;
    if (warp >= NN) return;
    int node = warp;
    int start = g_row[node], end = g_row[node + 1];

    int head = lane >> 3;
    int sub = lane & 7;
    float aldh = g_ald[node * 4 + head];
    int c4 = lane * 4;
    float4 acc = make_float4(0.f, 0.f, 0.f, 0.f);
    float den = 0.f;

    for (int base = start; base < end; base += 32) {
        int j = base + lane;
        int sj = (j < end) ? g_srcv[j] : 0;
        float er[4];
#pragma unroll
        for (int k = 0; k < 4; k++) {
            int s2 = __shfl_sync(0xffffffffu, sj, sub + 8 * k);
            float e = __ldg(&g_als[s2 * 4 + head]) + aldh;
            e = (e >= 0.f) ? e : 0.2f * e;
            er[k] = (base + sub + 8 * k < end) ? __expf(e) : 0.f;
        }
#pragma unroll
        for (int k8 = 0; k8 < 4; k8++) {
            if (base + 8 * k8 >= end) break;
            float ek = er[k8];
            int s[8];
            float w[8];
#pragma unroll
            for (int u = 0; u < 8; u++) {
                s[u] = __shfl_sync(0xffffffffu, sj, 8 * k8 + u);
                w[u] = __shfl_sync(0xffffffffu, ek, (head << 3) | u);
            }
            uint2 hv[8];
#pragma unroll
            for (int u = 0; u < 8; u++)
                hv[u] = *(const uint2*)(g_h01 + (size_t)s[u] * 128 + c4);
#pragma unroll
            for (int u = 0; u < 8; u++) {
                float2 fa = __half22float2(*reinterpret_cast<__half2*>(&hv[u].x));
                float2 fb = __half22float2(*reinterpret_cast<__half2*>(&hv[u].y));
                den += w[u];
                acc.x = fmaf(w[u], fa.x, acc.x);
                acc.y = fmaf(w[u], fa.y, acc.y);
                acc.z = fmaf(w[u], fb.x, acc.z);
                acc.w = fmaf(w[u], fb.y, acc.w);
            }
        }
    }

    float invd = 1.f / den;
    float4 bv = *(const float4*)&bias[c4];
    float r0 = fmaf(acc.x, invd, bv.x);
    float r1 = fmaf(acc.y, invd, bv.y);
    float r2 = fmaf(acc.z, invd, bv.z);
    float r3 = fmaf(acc.w, invd, bv.w);
    r0 = (r0 > 0.f) ? r0 : expm1f(r0);
    r1 = (r1 > 0.f) ? r1 : expm1f(r1);
    r2 = (r2 > 0.f) ? r2 : expm1f(r2);
    r3 = (r3 > 0.f) ? r3 : expm1f(r3);
    uint2 o;
    *reinterpret_cast<__half2*>(&o.x) = __floats2half2_rn(r0, r1);
    *reinterpret_cast<__half2*>(&o.y) = __floats2half2_rn(r2, r3);
    *(uint2*)(g_feat + (size_t)node * 128 + c4) = o;
}

// ---------------- layer 2: GEMM (Nout=40) + fused attention dots ---------------
__global__ void __launch_bounds__(256)
k_gemm40(const float* __restrict__ W2,
         const float* __restrict__ a_src2, const float* __restrict__ a_dst2) {
    __shared__ float Wt[128 * 44];
    __shared__ float Xs[32 * 128];
    int t = threadIdx.x;
    int row0 = blockIdx.x * 32;

    for (int idx = t; idx < 40 * 128; idx += 256) {
        int c = idx >> 7, k = idx & 127;
        Wt[k * 44 + c] = W2[idx];
    }
    for (int idx = t; idx < 32 * 32; idx += 256) {
        int r = idx >> 5, c4 = (idx & 31) * 4;
        int row = row0 + r;
        float4 v = make_float4(0.f, 0.f, 0.f, 0.f);
        if (row < NN) {
            uint2 hv = *(const uint2*)(g_feat + (size_t)row * 128 + c4);
            float2 fa = __half22float2(*reinterpret_cast<__half2*>(&hv.x));
            float2 fb = __half22float2(*reinterpret_cast<__half2*>(&hv.y));
            v = make_float4(fa.x, fa.y, fb.x, fb.y);
        }
        *(float4*)&Xs[r * 128 + c4] = v;
    }

    int cg = t & 7;
    int rg = t >> 3;
    float as[5], ad[5];
#pragma unroll
    for (int j = 0; j < 5; j++) {
        as[j] = __ldg(&a_src2[cg * 5 + j]);
        ad[j] = __ldg(&a_dst2[cg * 5 + j]);
    }
    __syncthreads();

    float acc[5] = {0.f, 0.f, 0.f, 0.f, 0.f};
#pragma unroll 4
    for (int k = 0; k < 128; k++) {
        float a = Xs[rg * 128 + k];
#pragma unroll
        for (int j = 0; j < 5; j++)
            acc[j] = fmaf(a, Wt[k * 44 + cg * 5 + j], acc[j]);
    }

    float ps = 0.f, pd = 0.f;
#pragma unroll
    for (int j = 0; j < 5; j++) {
        ps = fmaf(acc[j], as[j], ps);
        pd = fmaf(acc[j], ad[j], pd);
    }
    ps += __shfl_xor_sync(0xffffffffu, ps, 1);
    ps += __shfl_xor_sync(0xffffffffu, ps, 2);
    ps += __shfl_xor_sync(0xffffffffu, ps, 4);
    pd += __shfl_xor_sync(0xffffffffu, pd, 1);
    pd += __shfl_xor_sync(0xffffffffu, pd, 2);
    pd += __shfl_xor_sync(0xffffffffu, pd, 4);

    int row = row0 + rg;
    if (row < NN) {
#pragma unroll
        for (int j = 0; j < 5; j++)
            g_h2[(size_t)row * 40 + cg * 5 + j] = __float2half(acc[j]);
        if (cg == 0) {
            g_als[row] = ps;
            g_ald[row] = pd;
        }
    }
}

// ---- layer 2: single-pass agg (fp16 gather) + bias + log_softmax fused --------
__global__ void __launch_bounds__(256)
k_agg2(const float* __restrict__ b2, float* __restrict__ out) {
    int warp = (blockIdx.x * blockDim.x + threadIdx.x) >> 5;
    int lane = threadIdx.x & 31;
    if (warp >= NN) return;
    int node = warp;
    int start = g_row[node], end = g_row[node + 1];
    float aldn = g_ald[node];

    float acc0 = 0.f, acc1 = 0.f, den = 0.f;
    for (int base = start; base < end; base += 32) {
        int j = base + lane;
        int sj = (j < end) ? g_srcv[j] : 0;
        float e = __ldg(&g_als[sj]) + aldn;
        e = (e >= 0.f) ? e : 0.2f * e;
        float al = (j < end) ? __expf(e) : 0.f;
#pragma unroll
        for (int k8 = 0; k8 < 4; k8++) {
            if (base + 8 * k8 >= end) break;
            int s[8];
            float w[8];
#pragma unroll
            for (int u = 0; u < 8; u++) {
                s[u] = __shfl_sync(0xffffffffu, sj, 8 * k8 + u);
                w[u] = __shfl_sync(0xffffffffu, al, 8 * k8 + u);
            }
            float h0[8], h1[8];
#pragma unroll
            for (int u = 0; u < 8; u++) {
                const __half* hr = &g_h2[(size_t)s[u] * 40];
                h0[u] = __half2float(hr[lane]);
                h1[u] = (lane < 8) ? __half2float(hr[32 + lane]) : 0.f;
            }
#pragma unroll
            for (int u = 0; u < 8; u++) {
                den += w[u];
                acc0 = fmaf(w[u], h0[u], acc0);
                acc1 = fmaf(w[u], h1[u], acc1);
            }
        }
    }
    float invd = 1.f / den;

    float v0 = fmaf(acc0, invd, __ldg(&b2[lane]));
    float v1 = (lane < 8) ? fmaf(acc1, invd, __ldg(&b2[32 + lane])) : -1e30f;
    float mx = fmaxf(v0, v1);
#pragma unroll
    for (int off = 16; off > 0; off >>= 1)
        mx = fmaxf(mx, __shfl_xor_sync(0xffffffffu, mx, off));
    float se = __expf(v0 - mx) + ((lane < 8) ? __expf(v1 - mx) : 0.f);
#pragma unroll
    for (int off = 16; off > 0; off >>= 1)
        se += __shfl_xor_sync(0xffffffffu, se, off);
    float lse = mx + __logf(se);

    out[(size_t)node * 40 + lane] = v0 - lse;
    if (lane < 8) out[(size_t)node * 40 + 32 + lane] = v1 - lse;
}

// ---------------- launch -------------------------------------------------------
extern "C" void kernel_launch(void* const* d_in, const int* in_sizes, int n_in,
                              void* d_out, int out_size) {
    const float* x   = (const float*)d_in[0];
    const void*  ei  = d_in[1];
    const float* W0  = (const float*)d_in[2];
    const float* as0 = (const float*)d_in[3];
    const float* ad0 = (const float*)d_in[4];
    const float* b0  = (const float*)d_in[5];
    const float* W1  = (const float*)d_in[6];
    const float* as1 = (const float*)d_in[7];
    const float* ad1 = (const float*)d_in[8];
    const float* b1  = (const float*)d_in[9];
    const float* W2  = (const float*)d_in[10];
    const float* as2 = (const float*)d_in[11];
    const float* ad2 = (const float*)d_in[12];
    const float* b2  = (const float*)d_in[13];
    float* out = (float*)d_out;

    static cudaStream_t s2 = nullptr;
    static cudaEvent_t evA = nullptr, evB = nullptr;
    if (s2 == nullptr) {
        cudaStreamCreateWithFlags(&s2, cudaStreamNonBlocking);
        cudaEventCreateWithFlags(&evA, cudaEventDisableTiming);
        cudaEventCreateWithFlags(&evB, cudaEventDisableTiming);
        cudaFuncSetAttribute(k_gemm_mma, cudaFuncAttributeMaxDynamicSharedMemorySize, SMH_TOT);
    }

    const int TC_BLKS  = (NN + 127) / 128;        // 391
    const int AGG_BLKS = (NN * 32 + 255) / 256;   // one warp per node

    // init (detect + deg zero) — the only CSR prerequisites
    k_init<<<(NN + 511) / 512, 512>>>((const int*)ei);

    // fork: CSR build on s2, overlapped with W split + layer-0 GEMM on main
    cudaEventRecord(evA, 0);
    cudaStreamWaitEvent(s2, evA, 0);
    k_count<<<(ETOT + 511) / 512, 512, 0, s2>>>(ei);
    k_scan1<<<NB, SCAN_B, 0, s2>>>();
    k_scan23<<<NB, SCAN_B, 0, s2>>>();
    k_fill<<<(ETOT + 511) / 512, 512, 0, s2>>>(ei);
    cudaEventRecord(evB, s2);

    k_wsplit<<<(32768 + 511) / 512, 512>>>(W0, W1);
    k_gemm_mma<<<TC_BLKS, 512, SMH_TOT>>>(x, 0, 0, as0, ad0);

    // join: aggregation needs both CSR and h
    cudaStreamWaitEvent(0, evB, 0);
    k_agg<<<AGG_BLKS, 256>>>(b0);

    // layer 1
    k_gemm_mma<<<TC_BLKS, 512, SMH_TOT>>>(nullptr, 1, 1, as1, ad1);
    k_agg<<<AGG_BLKS, 256>>>(b1);

    // layer 2
    k_gemm40<<<(NN + 31) / 32, 256>>>(W2, as2, ad2);
    k_agg2<<<AGG_BLKS, 256>>>(b2, out);
}

// round 16
// speedup vs baseline: 1.2201x; 1.1715x over previous
#include <cuda_runtime.h>
#include <cuda_bf16.h>
#include <cuda_fp16.h>
#include <math.h>
#include <cstdint>

#define NN   50000
#define EE0  800000
#define ETOT 850000
#define NH   4
#define SCAN_B 512
#define NB   ((NN + SCAN_B - 1) / SCAN_B)   // 98

// ---------------- scratch (device globals; no allocation allowed) -------------
__device__ __align__(16) __half g_feat[(size_t)NN * 128];  // inter-layer feats (fp16)
__device__ __align__(16) __half g_h01[(size_t)NN * 128];   // layers 0/1 h (fp16)
__device__ __align__(16) __half g_h2[(size_t)NN * 40];     // layer 2 h (fp16)
__device__ __align__(16) float g_als[NN * NH];
__device__ __align__(16) float g_ald[NN * NH];
__device__ __align__(16) __nv_bfloat16 g_Whi[2][16384];
__device__ __align__(16) __nv_bfloat16 g_Wlo[2][16384];
__device__ __align__(16) __nv_bfloat16 g_W2hi[5120];
__device__ __align__(16) __nv_bfloat16 g_W2lo[5120];
__device__ int g_deg[NN];
__device__ int g_row[NN + 1];
__device__ int g_cur[NN];
__device__ int g_bsum[NB];
__device__ int g_srcv[ETOT];
__device__ int g_is64;

// ---------------- small helpers -----------------------------------------------
#define MMA_BF16(d, a, b) \
    asm volatile("mma.sync.aligned.m16n8k16.row.col.f32.bf16.bf16.f32 " \
        "{%0,%1,%2,%3}, {%4,%5,%6,%7}, {%8,%9}, {%0,%1,%2,%3};" \
        : "+f"((d)[0]), "+f"((d)[1]), "+f"((d)[2]), "+f"((d)[3]) \
        : "r"((a)[0]), "r"((a)[1]), "r"((a)[2]), "r"((a)[3]), "r"((b)[0]), "r"((b)[1]))

#define LDSM_X4(r0, r1, r2, r3, addr) \
    asm volatile("ldmatrix.sync.aligned.m8n8.x4.shared.b16 {%0,%1,%2,%3}, [%4];" \
        : "=r"(r0), "=r"(r1), "=r"(r2), "=r"(r3) : "r"(addr))

#define LDSM_X2(r0, r1, addr) \
    asm volatile("ldmatrix.sync.aligned.m8n8.x2.shared.b16 {%0,%1}, [%2];" \
        : "=r"(r0), "=r"(r1) : "r"(addr))

__device__ __forceinline__ uint32_t sm_u32(const void* p) {
    return (uint32_t)__cvta_generic_to_shared(p);
}
__device__ __forceinline__ void split_bf16(float x, __nv_bfloat16& h, __nv_bfloat16& l) {
    h = __float2bfloat16(x);
    l = __float2bfloat16(x - __bfloat162float(h));
}
__device__ __forceinline__ uint32_t bfpair(__nv_bfloat16 a, __nv_bfloat16 b) {
    return (uint32_t)__bfloat16_as_ushort(a) | ((uint32_t)__bfloat16_as_ushort(b) << 16);
}

// ---------------- edge access --------------------------------------------------
__device__ __forceinline__ void get_edge(const void* ei, int e, int& s, int& d) {
    if (e >= EE0) { s = e - EE0; d = s; return; }
    if (g_is64) {
        const long long* p = (const long long*)ei;
        s = (int)p[e];
        d = (int)p[EE0 + e];
    } else {
        const int* p = (const int*)ei;
        s = p[e];
        d = p[EE0 + e];
    }
}
__device__ __forceinline__ int get_dst(const void* ei, int e) {
    if (e >= EE0) return e - EE0;
    if (g_is64) return (int)((const long long*)ei)[EE0 + e];
    return ((const int*)ei)[EE0 + e];
}

// ---------------- init: dtype detect + deg zero (CSR prerequisites only) -------
__global__ void k_init(const int* __restrict__ ei32) {
    int i = blockIdx.x * blockDim.x + threadIdx.x;
    if (blockIdx.x == 0) {
        __shared__ int zc;
        if (threadIdx.x == 0) zc = 0;
        __syncthreads();
        int z = 0;
        for (int k = threadIdx.x; k < 1024; k += blockDim.x)
            if (ei32[2 * k + 1] == 0) z++;
        atomicAdd(&zc, z);
        __syncthreads();
        if (threadIdx.x == 0) g_is64 = (zc > 512) ? 1 : 0;
    }
    if (i < NN) g_deg[i] = 0;
}

// ---------------- W split (W0, W1, W2) -----------------------------------------
__global__ void k_wsplit(const float* __restrict__ W0, const float* __restrict__ W1,
                         const float* __restrict__ W2) {
    int i = blockIdx.x * blockDim.x + threadIdx.x;
    if (i < 16384) {
        split_bf16(W0[i], g_Whi[0][i], g_Wlo[0][i]);
    } else if (i < 32768) {
        split_bf16(W1[i - 16384], g_Whi[1][i - 16384], g_Wlo[1][i - 16384]);
    } else if (i < 37888) {
        split_bf16(W2[i - 32768], g_W2hi[i - 32768], g_W2lo[i - 32768]);
    }
}

// ---------------- CSR build ---------------------------------------------------
__global__ void k_count(const void* __restrict__ ei) {
    int e = blockIdx.x * blockDim.x + threadIdx.x;
    if (e >= ETOT) return;
    atomicAdd(&g_deg[get_dst(ei, e)], 1);
}

__global__ void k_scan1() {
    __shared__ int sm[SCAN_B];
    int t = threadIdx.x;
    int idx = blockIdx.x * SCAN_B + t;
    int v = (idx < NN) ? g_deg[idx] : 0;
    sm[t] = v;
    __syncthreads();
#pragma unroll
    for (int off = 1; off < SCAN_B; off <<= 1) {
        int p = (t >= off) ? sm[t - off] : 0;
        __syncthreads();
        sm[t] += p;
        __syncthreads();
    }
    if (idx < NN) g_row[idx] = sm[t] - v;
    if (t == SCAN_B - 1) g_bsum[blockIdx.x] = sm[t];
}

__global__ void k_scan23() {
    __shared__ int sm[128];
    int t = threadIdx.x;
    int b = blockIdx.x;
    if (t < 128) {
        sm[t] = (t < NB) ? g_bsum[t] : 0;
    }
    __syncthreads();
#pragma unroll
    for (int off = 1; off < 128; off <<= 1) {
        int p = 0;
        if (t < 128 && t >= off) p = sm[t - off];
        __syncthreads();
        if (t < 128) sm[t] += p;
        __syncthreads();
    }
    int boff = (b > 0) ? sm[b - 1] : 0;
    int idx = b * SCAN_B + t;
    if (idx < NN) {
        int r = g_row[idx] + boff;
        g_row[idx] = r;
        g_cur[idx] = r;
    }
    if (idx == 0) g_row[NN] = ETOT;
}

__global__ void k_fill(const void* __restrict__ ei) {
    int e = blockIdx.x * blockDim.x + threadIdx.x;
    if (e >= ETOT) return;
    int s, d;
    get_edge(ei, e, s, d);
    int pos = atomicAdd(&g_cur[d], 1);
    g_srcv[pos] = s;
}

// ======= bf16x3 GEMM via mma.sync + ldmatrix, 128x128 tile, fused att dots ====
#define SMH_XHI 1024
#define SMH_XLO (SMH_XHI + 128 * 136 * 2)
#define SMH_WHI (SMH_XLO + 128 * 136 * 2)
#define SMH_WLO (SMH_WHI + 128 * 136 * 2)
#define SMH_TOT (SMH_WLO + 128 * 136 * 2)   // 140288

__global__ void __launch_bounds__(512, 1)
k_gemm_mma(const float* __restrict__ xin, int use_gfeat, int widx,
           const float* __restrict__ a_src, const float* __restrict__ a_dst) {
    extern __shared__ char smem[];
    float* AS = (float*)(smem);
    float* AD = (float*)(smem + 512);
    __nv_bfloat16* Xhi = (__nv_bfloat16*)(smem + SMH_XHI);
    __nv_bfloat16* Xlo = (__nv_bfloat16*)(smem + SMH_XLO);
    __nv_bfloat16* Whi = (__nv_bfloat16*)(smem + SMH_WHI);
    __nv_bfloat16* Wlo = (__nv_bfloat16*)(smem + SMH_WLO);
    int tid = threadIdx.x;
    int row0 = blockIdx.x * 128;

    if (tid < 128) {
        AS[tid] = a_src[tid];
        AD[tid] = a_dst[tid];
    }
    for (int idx = tid; idx < 128 * 32; idx += 512) {
        int r = idx >> 5, c4 = (idx & 31) * 4;
        int row = row0 + r;
        float4 v = make_float4(0.f, 0.f, 0.f, 0.f);
        if (row < NN) {
            if (use_gfeat) {
                uint2 hv = *(const uint2*)(g_feat + (size_t)row * 128 + c4);
                float2 fa = __half22float2(*reinterpret_cast<__half2*>(&hv.x));
                float2 fb = __half22float2(*reinterpret_cast<__half2*>(&hv.y));
                v = make_float4(fa.x, fa.y, fb.x, fb.y);
            } else {
                v = *(const float4*)&xin[(size_t)row * 128 + c4];
            }
        }
        __nv_bfloat16 h0, h1, h2, h3, l0, l1, l2, l3;
        split_bf16(v.x, h0, l0);
        split_bf16(v.y, h1, l1);
        split_bf16(v.z, h2, l2);
        split_bf16(v.w, h3, l3);
        uint32_t* dh = (uint32_t*)(Xhi + r * 136 + c4);
        uint32_t* dl = (uint32_t*)(Xlo + r * 136 + c4);
        dh[0] = bfpair(h0, h1);
        dh[1] = bfpair(h2, h3);
        dl[0] = bfpair(l0, l1);
        dl[1] = bfpair(l2, l3);
    }
    {
        const __nv_bfloat16* whi = g_Whi[widx];
        const __nv_bfloat16* wlo = g_Wlo[widx];
        for (int idx = tid; idx < 2048; idx += 512) {
            int n = idx >> 4, kc = (idx & 15) * 8;
            *(uint4*)(Whi + n * 136 + kc) = *(const uint4*)(whi + n * 128 + kc);
            *(uint4*)(Wlo + n * 136 + kc) = *(const uint4*)(wlo + n * 128 + kc);
        }
    }
    __syncthreads();

    int w = tid >> 5;
    int lane = tid & 31;
    int g = lane >> 2;
    int tig = lane & 3;
    int rw = (w & 7) * 16;
    int cw = (w >> 3) * 64;

    uint32_t aoffH = sm_u32(Xhi + (rw + (lane & 15)) * 136 + ((lane >> 4) << 3));
    uint32_t aoffL = sm_u32(Xlo + (rw + (lane & 15)) * 136 + ((lane >> 4) << 3));
    uint32_t boffH = sm_u32(Whi + (cw + (lane & 7)) * 136 + (((lane >> 3) & 1) << 3));
    uint32_t boffL = sm_u32(Wlo + (cw + (lane & 7)) * 136 + (((lane >> 3) & 1) << 3));

    float acc[8][4];
#pragma unroll
    for (int i = 0; i < 8; i++)
#pragma unroll
        for (int j = 0; j < 4; j++) acc[i][j] = 0.f;

#pragma unroll
    for (int kt = 0; kt < 8; kt++) {
        uint32_t ka = (uint32_t)kt * 32;
        uint32_t ahi[4], alo[4];
        LDSM_X4(ahi[0], ahi[1], ahi[2], ahi[3], aoffH + ka);
        LDSM_X4(alo[0], alo[1], alo[2], alo[3], aoffL + ka);
#pragma unroll
        for (int nt = 0; nt < 8; nt++) {
            uint32_t nb = (uint32_t)nt * (8 * 136 * 2);
            uint32_t bhi[2], blo[2];
            LDSM_X2(bhi[0], bhi[1], boffH + nb + ka);
            LDSM_X2(blo[0], blo[1], boffL + nb + ka);
            MMA_BF16(acc[nt], ahi, bhi);
            MMA_BF16(acc[nt], ahi, blo);
            MMA_BF16(acc[nt], alo, bhi);
        }
    }

    int rowA = row0 + rw + g;
    int rowB = rowA + 8;
    int h0 = (w >> 3) * 2;
    float ps0[2] = {0.f, 0.f}, ps1[2] = {0.f, 0.f};
    float pd0[2] = {0.f, 0.f}, pd1[2] = {0.f, 0.f};
#pragma unroll
    for (int nt = 0; nt < 8; nt++) {
        int h = nt >> 2;
        int c = cw + nt * 8 + 2 * tig;
        float a0 = AS[c], a1 = AS[c + 1];
        float d0 = AD[c], d1 = AD[c + 1];
        ps0[h] += acc[nt][0] * a0 + acc[nt][1] * a1;
        ps1[h] += acc[nt][2] * a0 + acc[nt][3] * a1;
        pd0[h] += acc[nt][0] * d0 + acc[nt][1] * d1;
        pd1[h] += acc[nt][2] * d0 + acc[nt][3] * d1;
        if (rowA < NN)
            *(__half2*)&g_h01[(size_t)rowA * 128 + c] = __floats2half2_rn(acc[nt][0], acc[nt][1]);
        if (rowB < NN)
            *(__half2*)&g_h01[(size_t)rowB * 128 + c] = __floats2half2_rn(acc[nt][2], acc[nt][3]);
    }
#pragma unroll
    for (int h = 0; h < 2; h++) {
        ps0[h] += __shfl_xor_sync(0xffffffffu, ps0[h], 1);
        ps0[h] += __shfl_xor_sync(0xffffffffu, ps0[h], 2);
        ps1[h] += __shfl_xor_sync(0xffffffffu, ps1[h], 1);
        ps1[h] += __shfl_xor_sync(0xffffffffu, ps1[h], 2);
        pd0[h] += __shfl_xor_sync(0xffffffffu, pd0[h], 1);
        pd0[h] += __shfl_xor_sync(0xffffffffu, pd0[h], 2);
        pd1[h] += __shfl_xor_sync(0xffffffffu, pd1[h], 1);
        pd1[h] += __shfl_xor_sync(0xffffffffu, pd1[h], 2);
    }
    if (tig == 0) {
#pragma unroll
        for (int h = 0; h < 2; h++) {
            if (rowA < NN) {
                g_als[rowA * 4 + h0 + h] = ps0[h];
                g_ald[rowA * 4 + h0 + h] = pd0[h];
            }
            if (rowB < NN) {
                g_als[rowB * 4 + h0 + h] = ps1[h];
                g_ald[rowB * 4 + h0 + h] = pd1[h];
            }
        }
    }
}

// --- single-pass softmax + aggregation, fp16 gather, unrolled-8 (layers 0/1) ---
__global__ void __launch_bounds__(256)
k_agg(const float* __restrict__ bias) {
    int warp = (blockIdx.x * blockDim.x + threadIdx.x) >> 5;
    int lane = threadIdx.x & 31;
    if (warp >= NN) return;
    int node = warp;
    int start = g_row[node], end = g_row[node + 1];

    int head = lane >> 3;
    int sub = lane & 7;
    float aldh = g_ald[node * 4 + head];
    int c4 = lane * 4;
    float4 acc = make_float4(0.f, 0.f, 0.f, 0.f);
    float den = 0.f;

    for (int base = start; base < end; base += 32) {
        int j = base + lane;
        int sj = (j < end) ? g_srcv[j] : 0;
        float er[4];
#pragma unroll
        for (int k = 0; k < 4; k++) {
            int s2 = __shfl_sync(0xffffffffu, sj, sub + 8 * k);
            float e = __ldg(&g_als[s2 * 4 + head]) + aldh;
            e = (e >= 0.f) ? e : 0.2f * e;
            er[k] = (base + sub + 8 * k < end) ? __expf(e) : 0.f;
        }
#pragma unroll
        for (int k8 = 0; k8 < 4; k8++) {
            if (base + 8 * k8 >= end) break;
            float ek = er[k8];
            int s[8];
            float w[8];
#pragma unroll
            for (int u = 0; u < 8; u++) {
                s[u] = __shfl_sync(0xffffffffu, sj, 8 * k8 + u);
                w[u] = __shfl_sync(0xffffffffu, ek, (head << 3) | u);
            }
            uint2 hv[8];
#pragma unroll
            for (int u = 0; u < 8; u++)
                hv[u] = *(const uint2*)(g_h01 + (size_t)s[u] * 128 + c4);
#pragma unroll
            for (int u = 0; u < 8; u++) {
                float2 fa = __half22float2(*reinterpret_cast<__half2*>(&hv[u].x));
                float2 fb = __half22float2(*reinterpret_cast<__half2*>(&hv[u].y));
                den += w[u];
                acc.x = fmaf(w[u], fa.x, acc.x);
                acc.y = fmaf(w[u], fa.y, acc.y);
                acc.z = fmaf(w[u], fb.x, acc.z);
                acc.w = fmaf(w[u], fb.y, acc.w);
            }
        }
    }

    float invd = 1.f / den;
    float4 bv = *(const float4*)&bias[c4];
    float r0 = fmaf(acc.x, invd, bv.x);
    float r1 = fmaf(acc.y, invd, bv.y);
    float r2 = fmaf(acc.z, invd, bv.z);
    float r3 = fmaf(acc.w, invd, bv.w);
    r0 = (r0 > 0.f) ? r0 : expm1f(r0);
    r1 = (r1 > 0.f) ? r1 : expm1f(r1);
    r2 = (r2 > 0.f) ? r2 : expm1f(r2);
    r3 = (r3 > 0.f) ? r3 : expm1f(r3);
    uint2 o;
    *reinterpret_cast<__half2*>(&o.x) = __floats2half2_rn(r0, r1);
    *reinterpret_cast<__half2*>(&o.y) = __floats2half2_rn(r2, r3);
    *(uint2*)(g_feat + (size_t)node * 128 + c4) = o;
}

// ===== layer 2: bf16x3 mma GEMM (N=40 = 5 frags), fused att dots, fp16 out ====
#define SM3_XHI 1024
#define SM3_XLO (SM3_XHI + 128 * 136 * 2)
#define SM3_WHI (SM3_XLO + 128 * 136 * 2)
#define SM3_WLO (SM3_WHI + 40 * 136 * 2)
#define SM3_TOT (SM3_WLO + 40 * 136 * 2)   // 92416

__global__ void __launch_bounds__(256, 2)
k_gemm40_mma(const float* __restrict__ a_src2, const float* __restrict__ a_dst2) {
    extern __shared__ char smem[];
    float* AS = (float*)(smem);                 // 40 floats
    float* AD = (float*)(smem + 512);
    __nv_bfloat16* Xhi = (__nv_bfloat16*)(smem + SM3_XHI);
    __nv_bfloat16* Xlo = (__nv_bfloat16*)(smem + SM3_XLO);
    __nv_bfloat16* Whi = (__nv_bfloat16*)(smem + SM3_WHI);
    __nv_bfloat16* Wlo = (__nv_bfloat16*)(smem + SM3_WLO);
    int tid = threadIdx.x;
    int row0 = blockIdx.x * 128;

    if (tid < 40) {
        AS[tid] = a_src2[tid];
        AD[tid] = a_dst2[tid];
    }
    // stage X from g_feat (fp16) -> bf16 hi/lo
    for (int idx = tid; idx < 128 * 32; idx += 256) {
        int r = idx >> 5, c4 = (idx & 31) * 4;
        int row = row0 + r;
        float4 v = make_float4(0.f, 0.f, 0.f, 0.f);
        if (row < NN) {
            uint2 hv = *(const uint2*)(g_feat + (size_t)row * 128 + c4);
            float2 fa = __half22float2(*reinterpret_cast<__half2*>(&hv.x));
            float2 fb = __half22float2(*reinterpret_cast<__half2*>(&hv.y));
            v = make_float4(fa.x, fa.y, fb.x, fb.y);
        }
        __nv_bfloat16 h0, h1, h2, h3, l0, l1, l2, l3;
        split_bf16(v.x, h0, l0);
        split_bf16(v.y, h1, l1);
        split_bf16(v.z, h2, l2);
        split_bf16(v.w, h3, l3);
        uint32_t* dh = (uint32_t*)(Xhi + r * 136 + c4);
        uint32_t* dl = (uint32_t*)(Xlo + r * 136 + c4);
        dh[0] = bfpair(h0, h1);
        dh[1] = bfpair(h2, h3);
        dl[0] = bfpair(l0, l1);
        dl[1] = bfpair(l2, l3);
    }
    // stage W2 hi/lo (40 x 128)
    for (int idx = tid; idx < 640; idx += 256) {
        int n = idx >> 4, kc = (idx & 15) * 8;
        *(uint4*)(Whi + n * 136 + kc) = *(const uint4*)(g_W2hi + n * 128 + kc);
        *(uint4*)(Wlo + n * 136 + kc) = *(const uint4*)(g_W2lo + n * 128 + kc);
    }
    __syncthreads();

    int w = tid >> 5;          // 8 warps x 16 rows
    int lane = tid & 31;
    int g = lane >> 2;
    int tig = lane & 3;
    int rw = w * 16;

    uint32_t aoffH = sm_u32(Xhi + (rw + (lane & 15)) * 136 + ((lane >> 4) << 3));
    uint32_t aoffL = sm_u32(Xlo + (rw + (lane & 15)) * 136 + ((lane >> 4) << 3));
    uint32_t boffH = sm_u32(Whi + (lane & 7) * 136 + (((lane >> 3) & 1) << 3));
    uint32_t boffL = sm_u32(Wlo + (lane & 7) * 136 + (((lane >> 3) & 1) << 3));

    float acc[5][4];
#pragma unroll
    for (int i = 0; i < 5; i++)
#pragma unroll
        for (int j = 0; j < 4; j++) acc[i][j] = 0.f;

#pragma unroll
    for (int kt = 0; kt < 8; kt++) {
        uint32_t ka = (uint32_t)kt * 32;
        uint32_t ahi[4], alo[4];
        LDSM_X4(ahi[0], ahi[1], ahi[2], ahi[3], aoffH + ka);
        LDSM_X4(alo[0], alo[1], alo[2], alo[3], aoffL + ka);
#pragma unroll
        for (int nt = 0; nt < 5; nt++) {
            uint32_t nb = (uint32_t)nt * (8 * 136 * 2);
            uint32_t bhi[2], blo[2];
            LDSM_X2(bhi[0], bhi[1], boffH + nb + ka);
            LDSM_X2(blo[0], blo[1], boffL + nb + ka);
            MMA_BF16(acc[nt], ahi, bhi);
            MMA_BF16(acc[nt], ahi, blo);
            MMA_BF16(acc[nt], alo, bhi);
        }
    }

    int rowA = row0 + rw + g;
    int rowB = rowA + 8;
    float psA = 0.f, psB = 0.f, pdA = 0.f, pdB = 0.f;
#pragma unroll
    for (int nt = 0; nt < 5; nt++) {
        int c = nt * 8 + 2 * tig;
        float a0 = AS[c], a1 = AS[c + 1];
        float d0 = AD[c], d1 = AD[c + 1];
        psA += acc[nt][0] * a0 + acc[nt][1] * a1;
        psB += acc[nt][2] * a0 + acc[nt][3] * a1;
        pdA += acc[nt][0] * d0 + acc[nt][1] * d1;
        pdB += acc[nt][2] * d0 + acc[nt][3] * d1;
        if (rowA < NN)
            *(__half2*)&g_h2[(size_t)rowA * 40 + c] = __floats2half2_rn(acc[nt][0], acc[nt][1]);
        if (rowB < NN)
            *(__half2*)&g_h2[(size_t)rowB * 40 + c] = __floats2half2_rn(acc[nt][2], acc[nt][3]);
    }
    psA += __shfl_xor_sync(0xffffffffu, psA, 1);
    psA += __shfl_xor_sync(0xffffffffu, psA, 2);
    psB += __shfl_xor_sync(0xffffffffu, psB, 1);
    psB += __shfl_xor_sync(0xffffffffu, psB, 2);
    pdA += __shfl_xor_sync(0xffffffffu, pdA, 1);
    pdA += __shfl_xor_sync(0xffffffffu, pdA, 2);
    pdB += __shfl_xor_sync(0xffffffffu, pdB, 1);
    pdB += __shfl_xor_sync(0xffffffffu, pdB, 2);
    if (tig == 0) {
        if (rowA < NN) {
            g_als[rowA] = psA;
            g_ald[rowA] = pdA;
        }
        if (rowB < NN) {
            g_als[rowB] = psB;
            g_ald[rowB] = pdB;
        }
    }
}

// ---- layer 2: single-pass agg (fp16 gather) + bias + log_softmax fused --------
__global__ void __launch_bounds__(256)
k_agg2(const float* __restrict__ b2, float* __restrict__ out) {
    int warp = (blockIdx.x * blockDim.x + threadIdx.x) >> 5;
    int lane = threadIdx.x & 31;
    if (warp >= NN) return;
    int node = warp;
    int start = g_row[node], end = g_row[node + 1];
    float aldn = g_ald[node];

    float acc0 = 0.f, acc1 = 0.f, den = 0.f;
    for (int base = start; base < end; base += 32) {
        int j = base + lane;
        int sj = (j < end) ? g_srcv[j] : 0;
        float e = __ldg(&g_als[sj]) + aldn;
        e = (e >= 0.f) ? e : 0.2f * e;
        float al = (j < end) ? __expf(e) : 0.f;
#pragma unroll
        for (int k8 = 0; k8 < 4; k8++) {
            if (base + 8 * k8 >= end) break;
            int s[8];
            float w[8];
#pragma unroll
            for (int u = 0; u < 8; u++) {
                s[u] = __shfl_sync(0xffffffffu, sj, 8 * k8 + u);
                w[u] = __shfl_sync(0xffffffffu, al, 8 * k8 + u);
            }
            float h0[8], h1[8];
#pragma unroll
            for (int u = 0; u < 8; u++) {
                const __half* hr = &g_h2[(size_t)s[u] * 40];
                h0[u] = __half2float(hr[lane]);
                h1[u] = (lane < 8) ? __half2float(hr[32 + lane]) : 0.f;
            }
#pragma unroll
            for (int u = 0; u < 8; u++) {
                den += w[u];
                acc0 = fmaf(w[u], h0[u], acc0);
                acc1 = fmaf(w[u], h1[u], acc1);
            }
        }
    }
    float invd = 1.f / den;

    float v0 = fmaf(acc0, invd, __ldg(&b2[lane]));
    float v1 = (lane < 8) ? fmaf(acc1, invd, __ldg(&b2[32 + lane])) : -1e30f;
    float mx = fmaxf(v0, v1);
#pragma unroll
    for (int off = 16; off > 0; off >>= 1)
        mx = fmaxf(mx, __shfl_xor_sync(0xffffffffu, mx, off));
    float se = __expf(v0 - mx) + ((lane < 8) ? __expf(v1 - mx) : 0.f);
#pragma unroll
    for (int off = 16; off > 0; off >>= 1)
        se += __shfl_xor_sync(0xffffffffu, se, off);
    float lse = mx + __logf(se);

    out[(size_t)node * 40 + lane] = v0 - lse;
    if (lane < 8) out[(size_t)node * 40 + 32 + lane] = v1 - lse;
}

// ---------------- launch -------------------------------------------------------
extern "C" void kernel_launch(void* const* d_in, const int* in_sizes, int n_in,
                              void* d_out, int out_size) {
    const float* x   = (const float*)d_in[0];
    const void*  ei  = d_in[1];
    const float* W0  = (const float*)d_in[2];
    const float* as0 = (const float*)d_in[3];
    const float* ad0 = (const float*)d_in[4];
    const float* b0  = (const float*)d_in[5];
    const float* W1  = (const float*)d_in[6];
    const float* as1 = (const float*)d_in[7];
    const float* ad1 = (const float*)d_in[8];
    const float* b1  = (const float*)d_in[9];
    const float* W2  = (const float*)d_in[10];
    const float* as2 = (const float*)d_in[11];
    const float* ad2 = (const float*)d_in[12];
    const float* b2  = (const float*)d_in[13];
    float* out = (float*)d_out;

    static cudaStream_t s2 = nullptr;
    static cudaEvent_t evA = nullptr, evB = nullptr;
    if (s2 == nullptr) {
        cudaStreamCreateWithFlags(&s2, cudaStreamNonBlocking);
        cudaEventCreateWithFlags(&evA, cudaEventDisableTiming);
        cudaEventCreateWithFlags(&evB, cudaEventDisableTiming);
        cudaFuncSetAttribute(k_gemm_mma, cudaFuncAttributeMaxDynamicSharedMemorySize, SMH_TOT);
        cudaFuncSetAttribute(k_gemm40_mma, cudaFuncAttributeMaxDynamicSharedMemorySize, SM3_TOT);
    }

    const int TC_BLKS  = (NN + 127) / 128;        // 391
    const int AGG_BLKS = (NN * 32 + 255) / 256;   // one warp per node

    // init (detect + deg zero) — the only CSR prerequisites
    k_init<<<(NN + 511) / 512, 512>>>((const int*)ei);

    // fork: CSR build on s2, overlapped with W split + layer-0 GEMM on main
    cudaEventRecord(evA, 0);
    cudaStreamWaitEvent(s2, evA, 0);
    k_count<<<(ETOT + 511) / 512, 512, 0, s2>>>(ei);
    k_scan1<<<NB, SCAN_B, 0, s2>>>();
    k_scan23<<<NB, SCAN_B, 0, s2>>>();
    k_fill<<<(ETOT + 511) / 512, 512, 0, s2>>>(ei);
    cudaEventRecord(evB, s2);

    k_wsplit<<<(37888 + 511) / 512, 512>>>(W0, W1, W2);
    k_gemm_mma<<<TC_BLKS, 512, SMH_TOT>>>(x, 0, 0, as0, ad0);

    // join: aggregation needs both CSR and h
    cudaStreamWaitEvent(0, evB, 0);
    k_agg<<<AGG_BLKS, 256>>>(b0);

    // layer 1
    k_gemm_mma<<<TC_BLKS, 512, SMH_TOT>>>(nullptr, 1, 1, as1, ad1);
    k_agg<<<AGG_BLKS, 256>>>(b1);

    // layer 2
    k_gemm40_mma<<<TC_BLKS, 256, SM3_TOT>>>(as2, ad2);
    k_agg2<<<AGG_BLKS, 256>>>(b2, out);
}